// round 9
// baseline (speedup 1.0000x reference)
#include <cuda_runtime.h>
#include <cstdint>

#define GRID     128
#define NTHREADS 1024
#define NT       4096     // B*S tokens

typedef unsigned long long ull;

// ---- device globals ----
__device__ float g_Q[NT * 64];          // Q per token
__device__ float g_TEMB[4096 * 64];
__device__ unsigned g_arrive;
__device__ volatile unsigned g_release;

// ---- smem layout (floats), total 58112 = 232448 bytes (max) ----
#define OFF_WQKV 0            // [k][192]      12288
#define OFF_WFC  12288        // [k][256]      16384
#define OFF_WPR  28672        // [k(256)][64]  16384
#define OFF_BQ   45056        // bqkv 192
#define OFF_BF   45248        // bfc 256
#define OFF_X    45504        // 32 tokens pitch 65 = 2080
#define OFF_HA   47584        // h (LN out) / A landing zone, 2080
#define OFF_K    49664        // K[128] pitch 17 = 2176 (peer-pushed)
#define OFF_V    51840        // V[128] pitch 17 = 2176 (peer-pushed)
#define OFF_P    54016        // softmax P, 32 warps x 128 = 4096
#define OFF_HID  49664        // Phase-C hid, 32 x pitch257 = 8224 (overlays K/V/P)
#define SMEM_FLOATS 58112
#define SMEM_BYTES (SMEM_FLOATS * 4)   // 232448

// ---- packed f32x2 helpers ----
__device__ __forceinline__ ull bcast2(float x) {
    ull r; asm("mov.b64 %0,{%1,%1};" : "=l"(r) : "f"(x)); return r;
}
__device__ __forceinline__ void upk2(ull v, float& x, float& y) {
    asm("mov.b64 {%0,%1},%2;" : "=f"(x), "=f"(y) : "l"(v));
}
__device__ __forceinline__ void fma2(ull& d, ull a, ull b) {
    asm("fma.rn.f32x2 %0,%1,%2,%0;" : "+l"(d) : "l"(a), "l"(b));
}

// ---- cluster helpers ----
__device__ __forceinline__ uint32_t smem_u32(const void* p) {
    uint32_t a;
    asm("{ .reg .u64 t; cvta.to.shared.u64 t, %1; cvt.u32.u64 %0, t; }" : "=r"(a) : "l"(p));
    return a;
}
__device__ __forceinline__ void sts_cluster1(uint32_t laddr, int rank, float v) {
    uint32_t r;
    asm volatile("mapa.shared::cluster.u32 %0, %1, %2;" : "=r"(r) : "r"(laddr), "r"(rank));
    asm volatile("st.shared::cluster.f32 [%0], %1;" :: "r"(r), "f"(v) : "memory");
}
#define CLUSTER_BAR() do { \
    asm volatile("barrier.cluster.arrive.aligned;" ::: "memory"); \
    asm volatile("barrier.cluster.wait.aligned;"   ::: "memory"); \
} while (0)

__device__ __forceinline__ void grid_sync(unsigned gen) {
    __syncthreads();
    if (threadIdx.x == 0) {
        __threadfence();
        unsigned prev = atomicAdd(&g_arrive, 1u);
        if (prev == gen * GRID - 1u) {
            __threadfence();
            g_release = gen;
        } else {
            while (*(volatile unsigned*)&g_release < gen) { __nanosleep(32); }
        }
        __threadfence();
    }
    __syncthreads();
}

extern "C" __global__ void __launch_bounds__(NTHREADS, 1) __cluster_dims__(4, 1, 1)
lt37349035606833_kernel(
    const int*   __restrict__ idx,   const int*   __restrict__ nloops_p,
    const float* __restrict__ wte,   const float* __restrict__ wpe,
    const float* __restrict__ tw1,   const float* __restrict__ tb1,
    const float* __restrict__ tw2,   const float* __restrict__ tb2,
    const float* __restrict__ ln1g_, const float* __restrict__ ln1b_,
    const float* __restrict__ wqkv_, const float* __restrict__ bqkv_,
    const float* __restrict__ wo_,   const float* __restrict__ bo_,
    const float* __restrict__ ln2g_, const float* __restrict__ ln2b_,
    const float* __restrict__ wfc_,  const float* __restrict__ bfc_,
    const float* __restrict__ wpr_,  const float* __restrict__ bpr_,
    const float* __restrict__ lnfg_, const float* __restrict__ lnfb_,
    float* __restrict__ out)
{
    extern __shared__ float sm[];
    const int tid = threadIdx.x;
    const int blk = blockIdx.x;
    const int w = tid >> 5, l = tid & 31;
    const int nloops = *nloops_p;
    unsigned gen = g_release;
    const uint32_t smb = smem_u32(sm);

    // ---- stage weights/biases ----
    for (int i = tid; i < 12288; i += NTHREADS) sm[OFF_WQKV + i] = wqkv_[i];
    for (int i = tid; i < 16384; i += NTHREADS) {
        sm[OFF_WFC + i] = wfc_[i];
        sm[OFF_WPR + i] = wpr_[i];
    }
    if (tid < 192)                sm[OFF_BQ + tid] = bqkv_[tid];
    if (tid >= 256 && tid < 512)  sm[OFF_BF + tid - 256] = bfc_[tid - 256];

    // ln gamma/beta registerized (per-lane)
    const float ln1g0 = __ldg(ln1g_ + l), ln1g1 = __ldg(ln1g_ + 32 + l);
    const float ln1b0 = __ldg(ln1b_ + l), ln1b1 = __ldg(ln1b_ + 32 + l);
    const float ln2g0 = __ldg(ln2g_ + l), ln2g1 = __ldg(ln2g_ + 32 + l);
    const float ln2b0 = __ldg(ln2b_ + l), ln2b1 = __ldg(ln2b_ + 32 + l);

    // ---- initial x tile (pitch 65) ----
    const int t0 = blk * 32;
    for (int i = tid; i < 2048; i += NTHREADS) {
        int t = i >> 6, d = i & 63;
        int tok = t0 + t;
        sm[OFF_X + t * 65 + d] = wte[idx[tok] * 64 + d] + wpe[(tok & 127) * 64 + d];
    }
    __syncthreads();

    // ---- precompute temb (scratch in K region; grid_sync below) ----
    {
        float* sT = sm + OFF_K;
        for (int s = blk; s < nloops; s += GRID) {
            float tt = (float)s;
            if (tid < 128) {
                float f = __expf(-9.2103403719761836f * (float)tid / 128.0f);
                float a = tt * f;
                sT[tid]       = cosf(a);
                sT[128 + tid] = sinf(a);
            }
            __syncthreads();
            for (int j = tid; j < 1024; j += NTHREADS) {
                float z = tb1[j];
                for (int k = 0; k < 256; ++k) z += sT[k] * tw1[k * 1024 + j];
                sT[256 + j] = z / (1.0f + __expf(-z));
            }
            __syncthreads();
            if (tid < 64) {
                float z = tb2[tid];
                for (int k = 0; k < 1024; ++k) z += sT[256 + k] * tw2[k * 64 + tid];
                g_TEMB[s * 64 + tid] = z;
            }
            __syncthreads();
        }
    }
    grid_sync(++gen);

    const int bb = blk >> 2, rc = blk & 3;   // cluster rank == head index
    const int tbatt = bb * 128;
    float* sX   = sm + OFF_X;
    float* sHA  = sm + OFF_HA;
    float* sHid = sm + OFF_HID;
    const float* sK  = sm + OFF_K;
    const float* sV  = sm + OFF_V;
    const float* sWq = sm + OFF_WQKV;
    const float* sWf = sm + OFF_WFC;
    const float* sWp = sm + OFF_WPR;
    const float* sBq = sm + OFF_BQ;
    const float* sBf = sm + OFF_BF;

    for (int it = 0; it < nloops; ++it) {
        // ============ Phase A: x += temb; LN1 -> sHA; QKV + push ============
        {
            const float* temb = g_TEMB + it * 64;
            float tv0 = __ldg(temb + l), tv1 = __ldg(temb + 32 + l);
            float x0 = sX[w * 65 + l]      + tv0;
            float x1 = sX[w * 65 + 32 + l] + tv1;
            sX[w * 65 + l]      = x0;
            sX[w * 65 + 32 + l] = x1;
            float s1 = x0 + x1, s2 = x0 * x0 + x1 * x1;
            #pragma unroll
            for (int o = 16; o; o >>= 1) {
                s1 += __shfl_xor_sync(0xffffffffu, s1, o);
                s2 += __shfl_xor_sync(0xffffffffu, s2, o);
            }
            float mu = s1 * (1.0f / 64.0f);
            float rs = rsqrtf(s2 * (1.0f / 64.0f) - mu * mu + 1e-5f);
            sHA[w * 65 + l]      = (x0 - mu) * rs * ln1g0 + ln1b0;
            sHA[w * 65 + 32 + l] = (x1 - mu) * rs * ln1g1 + ln1b1;
        }
        __syncthreads();
        {   // QKV GEMM: warp -> 6 cols, lane -> token
            const int c0 = w * 6;
            const float* hAl = sHA + l * 65;
            ull acc[3] = {0, 0, 0};
            #pragma unroll 4
            for (int k = 0; k < 64; ++k) {
                ull h2 = bcast2(hAl[k]);
                const float* wr = sWq + k * 192 + c0;
                ull w0 = *(const ull*)(wr);
                ull w1 = *(const ull*)(wr + 2);
                ull w2 = *(const ull*)(wr + 4);
                fma2(acc[0], h2, w0); fma2(acc[1], h2, w1); fma2(acc[2], h2, w2);
            }
            const int tok = t0 + l;
            const int tkb = rc * 32 + l;
            #pragma unroll
            for (int j = 0; j < 3; ++j) {
                float v0, v1;
                upk2(acc[j], v0, v1);
                int p = c0 + 2 * j;
                v0 += sBq[p]; v1 += sBq[p + 1];
                if (p < 64) {
                    *(float2*)&g_Q[tok * 64 + p] = make_float2(v0, v1);
                } else if (p < 128) {
                    int dd = (p - 64) & 15, tr = (p - 64) >> 4;
                    uint32_t a = smb + (OFF_K + tkb * 17 + dd) * 4;
                    sts_cluster1(a,     tr, v0);
                    sts_cluster1(a + 4, tr, v1);
                } else {
                    int dd = (p - 128) & 15, tr = (p - 128) >> 4;
                    uint32_t a = smb + (OFF_V + tkb * 17 + dd) * 4;
                    sts_cluster1(a,     tr, v0);
                    sts_cluster1(a + 4, tr, v1);
                }
            }
        }
        CLUSTER_BAR();   // bar1: QKV delivered everywhere

        // ============ Phase B: attention for (bb, rc) ============
        {
            float* sP = sm + OFF_P + w * 128;
            const int d = l & 15, half = l >> 4;
            #pragma unroll 1
            for (int r = 0; r < 4; ++r) {
                const int qt = w + 32 * r;          // gq == r, warp-uniform
                const float4* qp = (const float4*)&g_Q[(tbatt + qt) * 64 + rc * 16];
                float4 qa = __ldcg(qp),     qb = __ldcg(qp + 1);
                float4 qc = __ldcg(qp + 2), qd = __ldcg(qp + 3);
                float q[16] = {qa.x, qa.y, qa.z, qa.w, qb.x, qb.y, qb.z, qb.w,
                               qc.x, qc.y, qc.z, qc.w, qd.x, qd.y, qd.z, qd.w};
                float e[4];
                float mx = -1e30f;
                #pragma unroll
                for (int g = 0; g < 4; ++g) {
                    if (g > r) break;
                    const float* Kr = sK + (32 * g + l) * 17;
                    float s = 0.f;
                    #pragma unroll
                    for (int dd = 0; dd < 16; ++dd) s += q[dd] * Kr[dd];
                    s = s * 0.25f + ((32 * g + l <= qt) ? 0.f : -1e9f);
                    e[g] = s;
                    mx = fmaxf(mx, s);
                }
                #pragma unroll
                for (int o = 16; o; o >>= 1) mx = fmaxf(mx, __shfl_xor_sync(0xffffffffu, mx, o));
                float es = 0.f;
                #pragma unroll
                for (int g = 0; g < 4; ++g) {
                    if (g > r) break;
                    e[g] = __expf(e[g] - mx);
                    es += e[g];
                }
                #pragma unroll
                for (int o = 16; o; o >>= 1) es += __shfl_xor_sync(0xffffffffu, es, o);
                float inv = 1.0f / es;
                #pragma unroll
                for (int g = 0; g < 4; ++g) {
                    if (g > r) break;
                    sP[32 * g + l] = e[g] * inv;
                }
                __syncwarp();
                float ov = 0.f;
                #pragma unroll
                for (int i = 0; i < 2; ++i) {
                    int g = half + 2 * i;
                    if (g <= r) {
                        const float* Pg = sP + 32 * g;
                        const float* Vg = sV + (32 * g) * 17 + d;
                        const float* P1 = Pg + 16 * half;
                        const float* V1 = Vg + (16 * half) * 17;
                        const float* P2 = Pg + 16 - 16 * half;
                        const float* V2 = Vg + (16 - 16 * half) * 17;
                        float pv = 0.f;
                        #pragma unroll
                        for (int k2 = 0; k2 < 16; ++k2) pv += P1[k2] * V1[k2 * 17];
                        #pragma unroll
                        for (int k2 = 0; k2 < 16; ++k2) pv += P2[k2] * V2[k2 * 17];
                        ov += pv;
                    }
                }
                ov += __shfl_xor_sync(0xffffffffu, ov, 16);
                if (half == 0) {   // push A to token-owner CTA (rank r), slot w
                    sts_cluster1(smb + (OFF_HA + w * 65 + rc * 16 + d) * 4, r, ov);
                }
                __syncwarp();
            }
        }
        CLUSTER_BAR();   // bar2: A delivered everywhere

        // ============ Phase C: o-proj + LN2 + MLP (lane = token) ============
        {   // o-proj: warp -> 2 cols
            const int c0o = w * 2;
            ull oac = 0;
            const float* sA = sHA + l * 65;
            #pragma unroll 4
            for (int k = 0; k < 64; ++k) {
                ull a2 = bcast2(sA[k]);
                ull wv = __ldg((const ull*)&wo_[k * 64 + c0o]);
                fma2(oac, a2, wv);
            }
            float o0, o1;
            upk2(oac, o0, o1);
            float2 bo2 = __ldg((const float2*)(bo_ + c0o));
            float* xr = sX + l * 65 + c0o;
            xr[0] += 0.1f * (o0 + bo2.x);
            xr[1] += 0.1f * (o1 + bo2.y);
        }
        __syncthreads();
        {   // LN2: warp -> token w -> h in sHA
            float x0 = sX[w * 65 + l], x1 = sX[w * 65 + 32 + l];
            float s1 = x0 + x1, s2 = x0 * x0 + x1 * x1;
            #pragma unroll
            for (int o = 16; o; o >>= 1) {
                s1 += __shfl_xor_sync(0xffffffffu, s1, o);
                s2 += __shfl_xor_sync(0xffffffffu, s2, o);
            }
            float mu = s1 * (1.f / 64.f);
            float rs = rsqrtf(s2 * (1.f / 64.f) - mu * mu + 1e-5f);
            sHA[w * 65 + l]      = (x0 - mu) * rs * ln2g0 + ln2b0;
            sHA[w * 65 + 32 + l] = (x1 - mu) * rs * ln2g1 + ln2b1;
        }
        __syncthreads();
        {   // FC: warp -> 8 cols; gelu; hid -> smem pitch 257
            const int c0f = w * 8;
            ull fac[4] = {0, 0, 0, 0};
            const float* sH = sHA + l * 65;
            #pragma unroll 4
            for (int k = 0; k < 64; ++k) {
                ull h2 = bcast2(sH[k]);
                const float* wr = sWf + k * 256 + c0f;
                ulonglong2 wa = *(const ulonglong2*)(wr);
                ulonglong2 wb = *(const ulonglong2*)(wr + 4);
                fma2(fac[0], h2, wa.x); fma2(fac[1], h2, wa.y);
                fma2(fac[2], h2, wb.x); fma2(fac[3], h2, wb.y);
            }
            float f[8];
            #pragma unroll
            for (int j = 0; j < 4; ++j) upk2(fac[j], f[2 * j], f[2 * j + 1]);
            float* hr = sHid + l * 257 + c0f;
            #pragma unroll
            for (int j = 0; j < 8; ++j) {
                float z = f[j] + sBf[c0f + j];
                float u = 0.7978845608028654f * (z + 0.044715f * z * z * z);
                float e2u = __expf(2.0f * u);
                float th = 1.0f - 2.0f / (e2u + 1.0f);
                hr[j] = 0.5f * z * (1.0f + th);
            }
        }
        __syncthreads();
        {   // PR: warp -> 2 cols; hid smem conflict-free
            const int c0p = w * 2;
            ull pac = 0;
            const float* hgl = sHid + l * 257;
            #pragma unroll 8
            for (int k = 0; k < 256; ++k) {
                ull h2 = bcast2(hgl[k]);
                ull wv = *(const ull*)&sWp[k * 64 + c0p];
                fma2(pac, h2, wv);
            }
            float p0, p1;
            upk2(pac, p0, p1);
            float2 bp2 = __ldg((const float2*)(bpr_ + c0p));
            float* xr = sX + l * 65 + c0p;
            xr[0] += 0.1f * (p0 + bp2.x);
            xr[1] += 0.1f * (p1 + bp2.y);
        }
        CLUSTER_BAR();   // bar3: hid scratch (K/V/P region) free before next push
    }

    // ================= final LN -> out =================
    {
        float g0 = __ldg(lnfg_ + l), g1 = __ldg(lnfg_ + 32 + l);
        float b0 = __ldg(lnfb_ + l), b1 = __ldg(lnfb_ + 32 + l);
        float x0 = sX[w * 65 + l], x1 = sX[w * 65 + 32 + l];
        float s1 = x0 + x1, s2 = x0 * x0 + x1 * x1;
        #pragma unroll
        for (int o = 16; o; o >>= 1) {
            s1 += __shfl_xor_sync(0xffffffffu, s1, o);
            s2 += __shfl_xor_sync(0xffffffffu, s2, o);
        }
        float mu = s1 * (1.f / 64.f);
        float rs = rsqrtf(s2 * (1.f / 64.f) - mu * mu + 1e-5f);
        out[(t0 + w) * 64 + l]      = (x0 - mu) * rs * g0 + b0;
        out[(t0 + w) * 64 + 32 + l] = (x1 - mu) * rs * g1 + b1;
    }
}

extern "C" void kernel_launch(void* const* d_in, const int* in_sizes, int n_in,
                              void* d_out, int out_size)
{
    (void)in_sizes; (void)n_in; (void)out_size;
    cudaFuncSetAttribute(lt37349035606833_kernel,
                         cudaFuncAttributeMaxDynamicSharedMemorySize, SMEM_BYTES);
    lt37349035606833_kernel<<<GRID, NTHREADS, SMEM_BYTES>>>(
        (const int*)  d_in[0],  (const int*)  d_in[1],
        (const float*)d_in[2],  (const float*)d_in[3],
        (const float*)d_in[4],  (const float*)d_in[5],
        (const float*)d_in[6],  (const float*)d_in[7],
        (const float*)d_in[8],  (const float*)d_in[9],
        (const float*)d_in[10], (const float*)d_in[11],
        (const float*)d_in[12], (const float*)d_in[13],
        (const float*)d_in[14], (const float*)d_in[15],
        (const float*)d_in[16], (const float*)d_in[17],
        (const float*)d_in[18], (const float*)d_in[19],
        (const float*)d_in[20], (const float*)d_in[21],
        (float*)d_out);
}

// round 10
// speedup vs baseline: 1.7259x; 1.7259x over previous
#include <cuda_runtime.h>
#include <cstdint>

#define GRID     128
#define NTHREADS 512
#define NT       4096     // B*S tokens

// ---- device globals ----
__device__ float g_Q[NT * 64];          // Q per token
__device__ float g_TEMB[4096 * 64];
__device__ unsigned g_arrive;
__device__ volatile unsigned g_release;

// ---- smem layout (floats) ----
#define OFF_WQKV 0            // [k][192]      12288
#define OFF_WFC  12288        // [k][256]      16384
#define OFF_WPR  28672        // [k(256)][64]  16384
#define OFF_B    45056        // 704
#define OFF_X    45760        // 32 tokens pitch 65 = 2080
#define OFF_K    47840        // K[128] pitch 17 = 2176 (peer-pushed)
#define OFF_V    50016        // V[128] pitch 17 = 2176 (peer-pushed)
#define OFF_HA   52192        // h (LN out) / A landing zone, 32x65 = 2080
#define OFF_P    54272        // softmax P, 16 warps x 128 = 2048
#define OFF_HID  47840        // Phase-C hid 32 x pitch257 = 8224 (overlays K/V/P: 8480)
#define SMEM_FLOATS 56320
#define SMEM_BYTES (SMEM_FLOATS * 4)   // 225280 <= 232448

// ---- packed f32x2 helpers ----
__device__ __forceinline__ unsigned long long bcast2(float x) {
    unsigned long long r; asm("mov.b64 %0,{%1,%1};" : "=l"(r) : "f"(x)); return r;
}
__device__ __forceinline__ void upk2(unsigned long long v, float& x, float& y) {
    asm("mov.b64 {%0,%1},%2;" : "=f"(x), "=f"(y) : "l"(v));
}
__device__ __forceinline__ void fma2(unsigned long long& d, unsigned long long a,
                                     unsigned long long b) {
    asm("fma.rn.f32x2 %0,%1,%2,%0;" : "+l"(d) : "l"(a), "l"(b));
}

// ---- cluster helpers ----
__device__ __forceinline__ uint32_t smem_u32(const void* p) {
    uint32_t a;
    asm("{ .reg .u64 t; cvta.to.shared.u64 t, %1; cvt.u32.u64 %0, t; }" : "=r"(a) : "l"(p));
    return a;
}
__device__ __forceinline__ void sts_cluster1(uint32_t laddr, int rank, float v) {
    uint32_t r;
    asm volatile("mapa.shared::cluster.u32 %0, %1, %2;" : "=r"(r) : "r"(laddr), "r"(rank));
    asm volatile("st.shared::cluster.f32 [%0], %1;" :: "r"(r), "f"(v) : "memory");
}
#define CLUSTER_BAR() do { \
    asm volatile("barrier.cluster.arrive.aligned;" ::: "memory"); \
    asm volatile("barrier.cluster.wait.aligned;"   ::: "memory"); \
} while (0)

__device__ __forceinline__ void grid_sync(unsigned gen) {
    __syncthreads();
    if (threadIdx.x == 0) {
        __threadfence();
        unsigned prev = atomicAdd(&g_arrive, 1u);
        if (prev == gen * GRID - 1u) {
            __threadfence();
            g_release = gen;
        } else {
            while (*(volatile unsigned*)&g_release < gen) { __nanosleep(32); }
        }
        __threadfence();
    }
    __syncthreads();
}

extern "C" __global__ void __launch_bounds__(NTHREADS, 1) __cluster_dims__(4, 1, 1)
lt37349035606833_kernel(
    const int*   __restrict__ idx,   const int*   __restrict__ nloops_p,
    const float* __restrict__ wte,   const float* __restrict__ wpe,
    const float* __restrict__ tw1,   const float* __restrict__ tb1,
    const float* __restrict__ tw2,   const float* __restrict__ tb2,
    const float* __restrict__ ln1g_, const float* __restrict__ ln1b_,
    const float* __restrict__ wqkv_, const float* __restrict__ bqkv_,
    const float* __restrict__ wo_,   const float* __restrict__ bo_,
    const float* __restrict__ ln2g_, const float* __restrict__ ln2b_,
    const float* __restrict__ wfc_,  const float* __restrict__ bfc_,
    const float* __restrict__ wpr_,  const float* __restrict__ bpr_,
    const float* __restrict__ lnfg_, const float* __restrict__ lnfb_,
    float* __restrict__ out)
{
    extern __shared__ float sm[];
    const int tid = threadIdx.x;
    const int blk = blockIdx.x;
    const int w = tid >> 5, l = tid & 31;
    const int nloops = *nloops_p;
    unsigned gen = g_release;
    const uint32_t smb = smem_u32(sm);

    // ---- stage weights/biases ----
    for (int i = tid; i < 12288; i += NTHREADS) sm[OFF_WQKV + i] = wqkv_[i];
    for (int i = tid; i < 16384; i += NTHREADS) {
        sm[OFF_WFC + i] = wfc_[i];
        sm[OFF_WPR + i] = wpr_[i];
    }
    if (tid < 192)                sm[OFF_B + tid] = bqkv_[tid];
    if (tid >= 192 && tid < 448)  sm[OFF_B + tid] = bfc_[tid - 192];
    if (tid < 64) {
        sm[OFF_B + 448 + tid] = ln1g_[tid];
        sm[OFF_B + 512 + tid] = ln1b_[tid];
        sm[OFF_B + 576 + tid] = ln2g_[tid];
        sm[OFF_B + 640 + tid] = ln2b_[tid];
    }

    // ---- initial x tile (pitch 65) ----
    const int t0 = blk * 32;
    for (int i = tid; i < 2048; i += NTHREADS) {
        int t = i >> 6, d = i & 63;
        int tok = t0 + t;
        sm[OFF_X + t * 65 + d] = wte[idx[tok] * 64 + d] + wpe[(tok & 127) * 64 + d];
    }
    __syncthreads();

    // ---- precompute temb (scratch in K/V region; grid_sync below) ----
    {
        float* sT = sm + OFF_K;
        for (int s = blk; s < nloops; s += GRID) {
            float tt = (float)s;
            if (tid < 128) {
                float f = __expf(-9.2103403719761836f * (float)tid / 128.0f);
                float a = tt * f;
                sT[tid]       = cosf(a);
                sT[128 + tid] = sinf(a);
            }
            __syncthreads();
            for (int j = tid; j < 1024; j += NTHREADS) {
                float z = tb1[j];
                for (int k = 0; k < 256; ++k) z += sT[k] * tw1[k * 1024 + j];
                sT[256 + j] = z / (1.0f + __expf(-z));
            }
            __syncthreads();
            if (tid < 64) {
                float z = tb2[tid];
                for (int k = 0; k < 1024; ++k) z += sT[256 + k] * tw2[k * 64 + tid];
                g_TEMB[s * 64 + tid] = z;
            }
            __syncthreads();
        }
    }
    grid_sync(++gen);

    const int bb = blk >> 2, rc = blk & 3;   // cluster rank == head index
    const int tbatt = bb * 128;
    float* sX   = sm + OFF_X;
    float* sHA  = sm + OFF_HA;               // h / A landing zone
    float* sHid = sm + OFF_HID;              // Phase-C hid (overlays K/V/P)
    const float* sK = sm + OFF_K;
    const float* sV = sm + OFF_V;
    const float* sWq = sm + OFF_WQKV;
    const float* sWf = sm + OFF_WFC;
    const float* sWp = sm + OFF_WPR;
    const float* sBq  = sm + OFF_B;
    const float* sBf  = sm + OFF_B + 192;
    const float* sL1g = sm + OFF_B + 448, *sL1b = sm + OFF_B + 512;
    const float* sL2g = sm + OFF_B + 576, *sL2b = sm + OFF_B + 640;

    for (int it = 0; it < nloops; ++it) {
        // ============ Phase A: x += temb; LN1 -> sHA; QKV + push ============
        {
            const float* temb = g_TEMB + it * 64;
            float tv0 = __ldg(temb + l), tv1 = __ldg(temb + 32 + l);
            #pragma unroll
            for (int t = 0; t < 2; ++t) {
                int lt = w * 2 + t;
                float x0 = sX[lt * 65 + l]      + tv0;
                float x1 = sX[lt * 65 + 32 + l] + tv1;
                sX[lt * 65 + l]      = x0;
                sX[lt * 65 + 32 + l] = x1;
                float s1 = x0 + x1, s2 = x0 * x0 + x1 * x1;
                #pragma unroll
                for (int o = 16; o; o >>= 1) {
                    s1 += __shfl_xor_sync(0xffffffffu, s1, o);
                    s2 += __shfl_xor_sync(0xffffffffu, s2, o);
                }
                float mu = s1 * (1.0f / 64.0f);
                float rs = rsqrtf(s2 * (1.0f / 64.0f) - mu * mu + 1e-5f);
                sHA[lt * 65 + l]      = (x0 - mu) * rs * sL1g[l]      + sL1b[l];
                sHA[lt * 65 + 32 + l] = (x1 - mu) * rs * sL1g[32 + l] + sL1b[32 + l];
            }
        }
        __syncthreads();
        {   // QKV GEMM: warp -> 12 cols, lane -> token; push K/V via DSMEM (scalar)
            const int c0 = w * 12;
            const float* hAl = sHA + l * 65;
            unsigned long long acc[6] = {0, 0, 0, 0, 0, 0};
            #pragma unroll 4
            for (int k = 0; k < 64; ++k) {
                unsigned long long h2 = bcast2(hAl[k]);
                const float* wr = sWq + k * 192 + c0;
                ulonglong2 wa = *(const ulonglong2*)(wr);
                ulonglong2 wb = *(const ulonglong2*)(wr + 4);
                ulonglong2 wc = *(const ulonglong2*)(wr + 8);
                fma2(acc[0], h2, wa.x); fma2(acc[1], h2, wa.y);
                fma2(acc[2], h2, wb.x); fma2(acc[3], h2, wb.y);
                fma2(acc[4], h2, wc.x); fma2(acc[5], h2, wc.y);
            }
            float c[12];
            #pragma unroll
            for (int j = 0; j < 6; ++j) upk2(acc[j], c[2 * j], c[2 * j + 1]);
            const int tok = t0 + l;          // global token
            const int tkb = rc * 32 + l;     // token within batch (0..127)
            #pragma unroll
            for (int g3 = 0; g3 < 3; ++g3) {
                int cg = c0 + 4 * g3;
                float v0 = c[4*g3]   + sBq[cg];
                float v1 = c[4*g3+1] + sBq[cg+1];
                float v2 = c[4*g3+2] + sBq[cg+2];
                float v3 = c[4*g3+3] + sBq[cg+3];
                if (cg < 64) {
                    *(float4*)&g_Q[tok * 64 + cg] = make_float4(v0, v1, v2, v3);
                } else if (cg < 128) {
                    int tr = (cg - 64) >> 4, d4 = (cg - 64) & 15;
                    uint32_t a = smb + (OFF_K + tkb * 17 + d4) * 4;
                    sts_cluster1(a,      tr, v0);
                    sts_cluster1(a + 4,  tr, v1);
                    sts_cluster1(a + 8,  tr, v2);
                    sts_cluster1(a + 12, tr, v3);
                } else {
                    int tr = (cg - 128) >> 4, d4 = (cg - 128) & 15;
                    uint32_t a = smb + (OFF_V + tkb * 17 + d4) * 4;
                    sts_cluster1(a,      tr, v0);
                    sts_cluster1(a + 4,  tr, v1);
                    sts_cluster1(a + 8,  tr, v2);
                    sts_cluster1(a + 12, tr, v3);
                }
            }
        }
        CLUSTER_BAR();   // bar1: QKV delivered everywhere

        // ============ Phase B: attention for (bb, rc); K/V local ============
        {
            float* sP = sm + OFF_P + w * 128;
            const int d = l & 15, half = l >> 4;
            #pragma unroll 1
            for (int r = 0; r < 8; ++r) {
                const int qt = w + 16 * r;          // interleaved -> warp balance
                const int gq = qt >> 5;
                const float4* qp = (const float4*)&g_Q[(tbatt + qt) * 64 + rc * 16];
                float4 qa = __ldcg(qp),     qb = __ldcg(qp + 1);
                float4 qc = __ldcg(qp + 2), qd = __ldcg(qp + 3);
                float q[16] = {qa.x, qa.y, qa.z, qa.w, qb.x, qb.y, qb.z, qb.w,
                               qc.x, qc.y, qc.z, qc.w, qd.x, qd.y, qd.z, qd.w};
                float e[4];
                float mx = -1e30f;
                #pragma unroll
                for (int g = 0; g < 4; ++g) {
                    if (g > gq) break;
                    const float* Kr = sK + (32 * g + l) * 17;
                    float s = 0.f;
                    #pragma unroll
                    for (int dd = 0; dd < 16; ++dd) s += q[dd] * Kr[dd];
                    s = s * 0.25f + ((32 * g + l <= qt) ? 0.f : -1e9f);
                    e[g] = s;
                    mx = fmaxf(mx, s);
                }
                #pragma unroll
                for (int o = 16; o; o >>= 1) mx = fmaxf(mx, __shfl_xor_sync(0xffffffffu, mx, o));
                float es = 0.f;
                #pragma unroll
                for (int g = 0; g < 4; ++g) {
                    if (g > gq) break;
                    e[g] = __expf(e[g] - mx);
                    es += e[g];
                }
                #pragma unroll
                for (int o = 16; o; o >>= 1) es += __shfl_xor_sync(0xffffffffu, es, o);
                float inv = 1.0f / es;
                #pragma unroll
                for (int g = 0; g < 4; ++g) {
                    if (g > gq) break;
                    sP[32 * g + l] = e[g] * inv;
                }
                __syncwarp();
                float ov = 0.f;
                #pragma unroll
                for (int i = 0; i < 2; ++i) {
                    int g = half + 2 * i;
                    if (g <= gq) {
                        const float* Pg = sP + 32 * g;
                        const float* Vg = sV + (32 * g) * 17 + d;
                        const float* P1 = Pg + 16 * half;
                        const float* V1 = Vg + (16 * half) * 17;
                        const float* P2 = Pg + 16 - 16 * half;
                        const float* V2 = Vg + (16 - 16 * half) * 17;
                        float pv = 0.f;
                        #pragma unroll
                        for (int k2 = 0; k2 < 16; ++k2) pv += P1[k2] * V1[k2 * 17];
                        #pragma unroll
                        for (int k2 = 0; k2 < 16; ++k2) pv += P2[k2] * V2[k2 * 17];
                        ov += pv;
                    }
                }
                ov += __shfl_xor_sync(0xffffffffu, ov, 16);
                if (half == 0) {   // push A to token-owner CTA's sHA
                    sts_cluster1(smb + (OFF_HA + (qt & 31) * 65 + rc * 16 + d) * 4,
                                 qt >> 5, ov);
                }
                __syncwarp();
            }
        }
        CLUSTER_BAR();   // bar2: A delivered everywhere; K/V/P dead from here

        // ============ Phase C: o-proj + LN2 + MLP (lane = token) ============
        {   // o-proj: warp -> 4 cols, lane -> token; A already in sHA
            const int c0o = w * 4;
            unsigned long long oac[2] = {0, 0};
            const float* sA = sHA + l * 65;
            #pragma unroll 4
            for (int k = 0; k < 64; ++k) {
                unsigned long long a2 = bcast2(sA[k]);
                ulonglong2 wv = __ldg((const ulonglong2*)&wo_[k * 64 + c0o]);
                fma2(oac[0], a2, wv.x); fma2(oac[1], a2, wv.y);
            }
            float o4[4];
            upk2(oac[0], o4[0], o4[1]); upk2(oac[1], o4[2], o4[3]);
            float4 bo4 = __ldg((const float4*)(bo_ + c0o));
            float* xr = sX + l * 65 + c0o;
            xr[0] += 0.1f * (o4[0] + bo4.x);
            xr[1] += 0.1f * (o4[1] + bo4.y);
            xr[2] += 0.1f * (o4[2] + bo4.z);
            xr[3] += 0.1f * (o4[3] + bo4.w);
        }
        __syncthreads();
        {   // LN2: 2 tokens/warp -> h in sHA (A fully consumed)
            #pragma unroll
            for (int t = 0; t < 2; ++t) {
                int lt = 2 * w + t;
                float x0 = sX[lt * 65 + l], x1 = sX[lt * 65 + 32 + l];
                float s1 = x0 + x1, s2 = x0 * x0 + x1 * x1;
                #pragma unroll
                for (int o = 16; o; o >>= 1) {
                    s1 += __shfl_xor_sync(0xffffffffu, s1, o);
                    s2 += __shfl_xor_sync(0xffffffffu, s2, o);
                }
                float mu = s1 * (1.f / 64.f);
                float rs = rsqrtf(s2 * (1.f / 64.f) - mu * mu + 1e-5f);
                sHA[lt * 65 + l]      = (x0 - mu) * rs * sL2g[l]      + sL2b[l];
                sHA[lt * 65 + 32 + l] = (x1 - mu) * rs * sL2g[32 + l] + sL2b[32 + l];
            }
        }
        __syncthreads();
        {   // FC: warp -> 16 cols, lane -> token; gelu; hid -> smem pitch 257
            const int c0f = w * 16;
            unsigned long long fac[8] = {0, 0, 0, 0, 0, 0, 0, 0};
            const float* sH = sHA + l * 65;
            #pragma unroll 2
            for (int k = 0; k < 64; ++k) {
                unsigned long long h2 = bcast2(sH[k]);
                const float* wr = sWf + k * 256 + c0f;
                ulonglong2 wa = *(const ulonglong2*)(wr);
                ulonglong2 wb = *(const ulonglong2*)(wr + 4);
                ulonglong2 wc = *(const ulonglong2*)(wr + 8);
                ulonglong2 wd = *(const ulonglong2*)(wr + 12);
                fma2(fac[0], h2, wa.x); fma2(fac[1], h2, wa.y);
                fma2(fac[2], h2, wb.x); fma2(fac[3], h2, wb.y);
                fma2(fac[4], h2, wc.x); fma2(fac[5], h2, wc.y);
                fma2(fac[6], h2, wd.x); fma2(fac[7], h2, wd.y);
            }
            float f[16];
            #pragma unroll
            for (int j = 0; j < 8; ++j) upk2(fac[j], f[2 * j], f[2 * j + 1]);
            float* hr = sHid + l * 257 + c0f;
            #pragma unroll
            for (int j = 0; j < 16; ++j) {
                float z = f[j] + sBf[c0f + j];
                float u = 0.7978845608028654f * (z + 0.044715f * z * z * z);
                float e2u = __expf(2.0f * u);
                float th = 1.0f - 2.0f / (e2u + 1.0f);
                hr[j] = 0.5f * z * (1.0f + th);
            }
        }
        __syncthreads();
        {   // PR: warp -> 4 cols, lane -> token; hid from smem (conflict-free)
            const int c0p = w * 4;
            unsigned long long pac[2] = {0, 0};
            const float* hgl = sHid + l * 257;
            #pragma unroll 8
            for (int k = 0; k < 256; ++k) {
                unsigned long long h2 = bcast2(hgl[k]);
                ulonglong2 wv = *(const ulonglong2*)&sWp[k * 64 + c0p];
                fma2(pac[0], h2, wv.x); fma2(pac[1], h2, wv.y);
            }
            float p4[4];
            upk2(pac[0], p4[0], p4[1]); upk2(pac[1], p4[2], p4[3]);
            float4 bp4 = __ldg((const float4*)(bpr_ + c0p));
            float* xr = sX + l * 65 + c0p;
            xr[0] += 0.1f * (p4[0] + bp4.x);
            xr[1] += 0.1f * (p4[1] + bp4.y);
            xr[2] += 0.1f * (p4[2] + bp4.z);
            xr[3] += 0.1f * (p4[3] + bp4.w);
        }
        CLUSTER_BAR();   // bar3: hid reads done before peers push next K/V
    }

    // ================= final LN -> out =================
    {
        float g0 = __ldg(lnfg_ + l), g1 = __ldg(lnfg_ + 32 + l);
        float b0 = __ldg(lnfb_ + l), b1 = __ldg(lnfb_ + 32 + l);
        #pragma unroll
        for (int t = 0; t < 2; ++t) {
            int lt = 2 * w + t;
            float x0 = sX[lt * 65 + l], x1 = sX[lt * 65 + 32 + l];
            float s1 = x0 + x1, s2 = x0 * x0 + x1 * x1;
            #pragma unroll
            for (int o = 16; o; o >>= 1) {
                s1 += __shfl_xor_sync(0xffffffffu, s1, o);
                s2 += __shfl_xor_sync(0xffffffffu, s2, o);
            }
            float mu = s1 * (1.f / 64.f);
            float rs = rsqrtf(s2 * (1.f / 64.f) - mu * mu + 1e-5f);
            out[(t0 + lt) * 64 + l]      = (x0 - mu) * rs * g0 + b0;
            out[(t0 + lt) * 64 + 32 + l] = (x1 - mu) * rs * g1 + b1;
        }
    }
}

extern "C" void kernel_launch(void* const* d_in, const int* in_sizes, int n_in,
                              void* d_out, int out_size)
{
    (void)in_sizes; (void)n_in; (void)out_size;
    cudaFuncSetAttribute(lt37349035606833_kernel,
                         cudaFuncAttributeMaxDynamicSharedMemorySize, SMEM_BYTES);
    lt37349035606833_kernel<<<GRID, NTHREADS, SMEM_BYTES>>>(
        (const int*)  d_in[0],  (const int*)  d_in[1],
        (const float*)d_in[2],  (const float*)d_in[3],
        (const float*)d_in[4],  (const float*)d_in[5],
        (const float*)d_in[6],  (const float*)d_in[7],
        (const float*)d_in[8],  (const float*)d_in[9],
        (const float*)d_in[10], (const float*)d_in[11],
        (const float*)d_in[12], (const float*)d_in[13],
        (const float*)d_in[14], (const float*)d_in[15],
        (const float*)d_in[16], (const float*)d_in[17],
        (const float*)d_in[18], (const float*)d_in[19],
        (const float*)d_in[20], (const float*)d_in[21],
        (float*)d_out);
}

// round 11
// speedup vs baseline: 1.7273x; 1.0008x over previous
#include <cuda_runtime.h>
#include <cstdint>

#define GRID     128
#define NTHREADS 512
#define NT       4096     // B*S tokens

// ---- device globals ----
__device__ float g_Q[NT * 64];          // Q per token
__device__ float g_TEMB[4096 * 64];
__device__ unsigned g_arrive;
__device__ volatile unsigned g_release;

// ---- smem layout (floats) ----
#define OFF_WQKV 0            // [k][192]      12288
#define OFF_WFC  12288        // [k][256]      16384
#define OFF_WPR  28672        // [k(256)][64]  16384
#define OFF_B    45056        // 704
#define OFF_X    45760        // 32 tokens pitch 65 = 2080
#define OFF_K    47840        // K[128] pitch 17 = 2176 (peer-pushed)
#define OFF_V    50016        // V[128] pitch 17 = 2176 (peer-pushed)
#define OFF_HA   52192        // h (LN out) / A landing zone, 32x65 = 2080
#define OFF_P    54272        // softmax P, 16 warps x 128 = 2048
#define OFF_HID  47840        // Phase-C hid 32 x pitch257 = 8224 (overlays K/V/P: 8480)
#define SMEM_FLOATS 56320
#define SMEM_BYTES (SMEM_FLOATS * 4)   // 225280 <= 232448

// ---- packed f32x2 helpers ----
__device__ __forceinline__ unsigned long long bcast2(float x) {
    unsigned long long r; asm("mov.b64 %0,{%1,%1};" : "=l"(r) : "f"(x)); return r;
}
__device__ __forceinline__ void upk2(unsigned long long v, float& x, float& y) {
    asm("mov.b64 {%0,%1},%2;" : "=f"(x), "=f"(y) : "l"(v));
}
__device__ __forceinline__ void fma2(unsigned long long& d, unsigned long long a,
                                     unsigned long long b) {
    asm("fma.rn.f32x2 %0,%1,%2,%0;" : "+l"(d) : "l"(a), "l"(b));
}

// ---- cluster helpers ----
__device__ __forceinline__ uint32_t smem_u32(const void* p) {
    uint32_t a;
    asm("{ .reg .u64 t; cvta.to.shared.u64 t, %1; cvt.u32.u64 %0, t; }" : "=r"(a) : "l"(p));
    return a;
}
__device__ __forceinline__ void sts_cluster1(uint32_t laddr, int rank, float v) {
    uint32_t r;
    asm volatile("mapa.shared::cluster.u32 %0, %1, %2;" : "=r"(r) : "r"(laddr), "r"(rank));
    asm volatile("st.shared::cluster.f32 [%0], %1;" :: "r"(r), "f"(v) : "memory");
}
#define CLUSTER_BAR() do { \
    asm volatile("barrier.cluster.arrive.aligned;" ::: "memory"); \
    asm volatile("barrier.cluster.wait.aligned;"   ::: "memory"); \
} while (0)

__device__ __forceinline__ void grid_sync(unsigned gen) {
    __syncthreads();
    if (threadIdx.x == 0) {
        __threadfence();
        unsigned prev = atomicAdd(&g_arrive, 1u);
        if (prev == gen * GRID - 1u) {
            __threadfence();
            g_release = gen;
        } else {
            while (*(volatile unsigned*)&g_release < gen) { __nanosleep(32); }
        }
        __threadfence();
    }
    __syncthreads();
}

extern "C" __global__ void __launch_bounds__(NTHREADS, 1) __cluster_dims__(4, 1, 1)
lt37349035606833_kernel(
    const int*   __restrict__ idx,   const int*   __restrict__ nloops_p,
    const float* __restrict__ wte,   const float* __restrict__ wpe,
    const float* __restrict__ tw1,   const float* __restrict__ tb1,
    const float* __restrict__ tw2,   const float* __restrict__ tb2,
    const float* __restrict__ ln1g_, const float* __restrict__ ln1b_,
    const float* __restrict__ wqkv_, const float* __restrict__ bqkv_,
    const float* __restrict__ wo_,   const float* __restrict__ bo_,
    const float* __restrict__ ln2g_, const float* __restrict__ ln2b_,
    const float* __restrict__ wfc_,  const float* __restrict__ bfc_,
    const float* __restrict__ wpr_,  const float* __restrict__ bpr_,
    const float* __restrict__ lnfg_, const float* __restrict__ lnfb_,
    float* __restrict__ out)
{
    extern __shared__ float sm[];
    const int tid = threadIdx.x;
    const int blk = blockIdx.x;
    const int w = tid >> 5, l = tid & 31;
    const int nloops = *nloops_p;
    unsigned gen = g_release;
    const uint32_t smb = smem_u32(sm);

    // ---- stage weights/biases ----
    for (int i = tid; i < 12288; i += NTHREADS) sm[OFF_WQKV + i] = wqkv_[i];
    for (int i = tid; i < 16384; i += NTHREADS) {
        sm[OFF_WFC + i] = wfc_[i];
        sm[OFF_WPR + i] = wpr_[i];
    }
    if (tid < 192)                sm[OFF_B + tid] = bqkv_[tid];
    if (tid >= 192 && tid < 448)  sm[OFF_B + tid] = bfc_[tid - 192];
    if (tid < 64) {
        sm[OFF_B + 448 + tid] = ln1g_[tid];
        sm[OFF_B + 512 + tid] = ln1b_[tid];
        sm[OFF_B + 576 + tid] = ln2g_[tid];
        sm[OFF_B + 640 + tid] = ln2b_[tid];
    }

    // ---- initial x tile (pitch 65) ----
    const int t0 = blk * 32;
    for (int i = tid; i < 2048; i += NTHREADS) {
        int t = i >> 6, d = i & 63;
        int tok = t0 + t;
        sm[OFF_X + t * 65 + d] = wte[idx[tok] * 64 + d] + wpe[(tok & 127) * 64 + d];
    }
    __syncthreads();

    // ---- precompute temb (scratch in K/V region; grid_sync below) ----
    {
        float* sT = sm + OFF_K;
        for (int s = blk; s < nloops; s += GRID) {
            float tt = (float)s;
            if (tid < 128) {
                float f = __expf(-9.2103403719761836f * (float)tid / 128.0f);
                float a = tt * f;
                sT[tid]       = cosf(a);
                sT[128 + tid] = sinf(a);
            }
            __syncthreads();
            for (int j = tid; j < 1024; j += NTHREADS) {
                float z = tb1[j];
                for (int k = 0; k < 256; ++k) z += sT[k] * tw1[k * 1024 + j];
                sT[256 + j] = z / (1.0f + __expf(-z));
            }
            __syncthreads();
            if (tid < 64) {
                float z = tb2[tid];
                for (int k = 0; k < 1024; ++k) z += sT[256 + k] * tw2[k * 64 + tid];
                g_TEMB[s * 64 + tid] = z;
            }
            __syncthreads();
        }
    }
    grid_sync(++gen);

    const int bb = blk >> 2, rc = blk & 3;   // cluster rank == head index
    const int tbatt = bb * 128;
    float* sX   = sm + OFF_X;
    float* sHA  = sm + OFF_HA;               // h / A landing zone
    float* sHid = sm + OFF_HID;              // Phase-C hid (overlays K/V/P)
    const float* sK = sm + OFF_K;
    const float* sV = sm + OFF_V;
    const float* sWq = sm + OFF_WQKV;
    const float* sWf = sm + OFF_WFC;
    const float* sWp = sm + OFF_WPR;
    const float* sBq  = sm + OFF_B;
    const float* sBf  = sm + OFF_B + 192;
    const float* sL1g = sm + OFF_B + 448, *sL1b = sm + OFF_B + 512;
    const float* sL2g = sm + OFF_B + 576, *sL2b = sm + OFF_B + 640;

    for (int it = 0; it < nloops; ++it) {
        // ============ Phase A: x += temb; LN1 -> sHA; QKV + push ============
        {
            const float* temb = g_TEMB + it * 64;
            float tv0 = __ldg(temb + l), tv1 = __ldg(temb + 32 + l);
            #pragma unroll
            for (int t = 0; t < 2; ++t) {
                int lt = w * 2 + t;
                float x0 = sX[lt * 65 + l]      + tv0;
                float x1 = sX[lt * 65 + 32 + l] + tv1;
                sX[lt * 65 + l]      = x0;
                sX[lt * 65 + 32 + l] = x1;
                float s1 = x0 + x1, s2 = x0 * x0 + x1 * x1;
                #pragma unroll
                for (int o = 16; o; o >>= 1) {
                    s1 += __shfl_xor_sync(0xffffffffu, s1, o);
                    s2 += __shfl_xor_sync(0xffffffffu, s2, o);
                }
                float mu = s1 * (1.0f / 64.0f);
                float rs = rsqrtf(s2 * (1.0f / 64.0f) - mu * mu + 1e-5f);
                sHA[lt * 65 + l]      = (x0 - mu) * rs * sL1g[l]      + sL1b[l];
                sHA[lt * 65 + 32 + l] = (x1 - mu) * rs * sL1g[32 + l] + sL1b[32 + l];
            }
        }
        __syncthreads();
        {   // QKV GEMM: warp -> 12 cols, lane -> token; push K/V via DSMEM (scalar)
            const int c0 = w * 12;
            const float* hAl = sHA + l * 65;
            unsigned long long acc[6] = {0, 0, 0, 0, 0, 0};
            #pragma unroll 4
            for (int k = 0; k < 64; ++k) {
                unsigned long long h2 = bcast2(hAl[k]);
                const float* wr = sWq + k * 192 + c0;
                ulonglong2 wa = *(const ulonglong2*)(wr);
                ulonglong2 wb = *(const ulonglong2*)(wr + 4);
                ulonglong2 wc = *(const ulonglong2*)(wr + 8);
                fma2(acc[0], h2, wa.x); fma2(acc[1], h2, wa.y);
                fma2(acc[2], h2, wb.x); fma2(acc[3], h2, wb.y);
                fma2(acc[4], h2, wc.x); fma2(acc[5], h2, wc.y);
            }
            float c[12];
            #pragma unroll
            for (int j = 0; j < 6; ++j) upk2(acc[j], c[2 * j], c[2 * j + 1]);
            const int tok = t0 + l;          // global token
            const int tkb = rc * 32 + l;     // token within batch (0..127)
            #pragma unroll
            for (int g3 = 0; g3 < 3; ++g3) {
                int cg = c0 + 4 * g3;
                float v0 = c[4*g3]   + sBq[cg];
                float v1 = c[4*g3+1] + sBq[cg+1];
                float v2 = c[4*g3+2] + sBq[cg+2];
                float v3 = c[4*g3+3] + sBq[cg+3];
                if (cg < 64) {
                    *(float4*)&g_Q[tok * 64 + cg] = make_float4(v0, v1, v2, v3);
                } else if (cg < 128) {
                    int tr = (cg - 64) >> 4, d4 = (cg - 64) & 15;
                    uint32_t a = smb + (OFF_K + tkb * 17 + d4) * 4;
                    sts_cluster1(a,      tr, v0);
                    sts_cluster1(a + 4,  tr, v1);
                    sts_cluster1(a + 8,  tr, v2);
                    sts_cluster1(a + 12, tr, v3);
                } else {
                    int tr = (cg - 128) >> 4, d4 = (cg - 128) & 15;
                    uint32_t a = smb + (OFF_V + tkb * 17 + d4) * 4;
                    sts_cluster1(a,      tr, v0);
                    sts_cluster1(a + 4,  tr, v1);
                    sts_cluster1(a + 8,  tr, v2);
                    sts_cluster1(a + 12, tr, v3);
                }
            }
        }
        CLUSTER_BAR();   // bar1: QKV delivered everywhere

        // ============ Phase B: attention for (bb, rc); K/V local ============
        {
            float* sP = sm + OFF_P + w * 128;
            const int d = l & 15, half = l >> 4;
            #pragma unroll 1
            for (int r = 0; r < 8; ++r) {
                const int qt = w + 16 * r;          // interleaved -> warp balance
                const int gq = qt >> 5;
                const float4* qp = (const float4*)&g_Q[(tbatt + qt) * 64 + rc * 16];
                float4 qa = __ldcg(qp),     qb = __ldcg(qp + 1);
                float4 qc = __ldcg(qp + 2), qd = __ldcg(qp + 3);
                float q[16] = {qa.x, qa.y, qa.z, qa.w, qb.x, qb.y, qb.z, qb.w,
                               qc.x, qc.y, qc.z, qc.w, qd.x, qd.y, qd.z, qd.w};
                float e[4];
                float mx = -1e30f;
                #pragma unroll
                for (int g = 0; g < 4; ++g) {
                    if (g > gq) break;
                    const float* Kr = sK + (32 * g + l) * 17;
                    float s = 0.f;
                    #pragma unroll
                    for (int dd = 0; dd < 16; ++dd) s += q[dd] * Kr[dd];
                    s = s * 0.25f + ((32 * g + l <= qt) ? 0.f : -1e9f);
                    e[g] = s;
                    mx = fmaxf(mx, s);
                }
                #pragma unroll
                for (int o = 16; o; o >>= 1) mx = fmaxf(mx, __shfl_xor_sync(0xffffffffu, mx, o));
                float es = 0.f;
                #pragma unroll
                for (int g = 0; g < 4; ++g) {
                    if (g > gq) break;
                    e[g] = __expf(e[g] - mx);
                    es += e[g];
                }
                #pragma unroll
                for (int o = 16; o; o >>= 1) es += __shfl_xor_sync(0xffffffffu, es, o);
                float inv = 1.0f / es;
                #pragma unroll
                for (int g = 0; g < 4; ++g) {
                    if (g > gq) break;
                    sP[32 * g + l] = e[g] * inv;
                }
                __syncwarp();
                float ov = 0.f;
                #pragma unroll
                for (int i = 0; i < 2; ++i) {
                    int g = half + 2 * i;
                    if (g <= gq) {
                        const float* Pg = sP + 32 * g;
                        const float* Vg = sV + (32 * g) * 17 + d;
                        const float* P1 = Pg + 16 * half;
                        const float* V1 = Vg + (16 * half) * 17;
                        const float* P2 = Pg + 16 - 16 * half;
                        const float* V2 = Vg + (16 - 16 * half) * 17;
                        float pv = 0.f;
                        #pragma unroll
                        for (int k2 = 0; k2 < 16; ++k2) pv += P1[k2] * V1[k2 * 17];
                        #pragma unroll
                        for (int k2 = 0; k2 < 16; ++k2) pv += P2[k2] * V2[k2 * 17];
                        ov += pv;
                    }
                }
                ov += __shfl_xor_sync(0xffffffffu, ov, 16);
                if (half == 0) {   // push A to token-owner CTA's sHA
                    sts_cluster1(smb + (OFF_HA + (qt & 31) * 65 + rc * 16 + d) * 4,
                                 qt >> 5, ov);
                }
                __syncwarp();
            }
        }
        CLUSTER_BAR();   // bar2: A delivered everywhere; K/V/P dead from here

        // ============ Phase C: o-proj + LN2 + MLP (lane = token) ============
        {   // o-proj: warp -> 4 cols, lane -> token; A already in sHA
            const int c0o = w * 4;
            unsigned long long oac[2] = {0, 0};
            const float* sA = sHA + l * 65;
            #pragma unroll 4
            for (int k = 0; k < 64; ++k) {
                unsigned long long a2 = bcast2(sA[k]);
                ulonglong2 wv = __ldg((const ulonglong2*)&wo_[k * 64 + c0o]);
                fma2(oac[0], a2, wv.x); fma2(oac[1], a2, wv.y);
            }
            float o4[4];
            upk2(oac[0], o4[0], o4[1]); upk2(oac[1], o4[2], o4[3]);
            float4 bo4 = __ldg((const float4*)(bo_ + c0o));
            float* xr = sX + l * 65 + c0o;
            xr[0] += 0.1f * (o4[0] + bo4.x);
            xr[1] += 0.1f * (o4[1] + bo4.y);
            xr[2] += 0.1f * (o4[2] + bo4.z);
            xr[3] += 0.1f * (o4[3] + bo4.w);
        }
        __syncthreads();
        {   // LN2: 2 tokens/warp -> h in sHA (A fully consumed)
            #pragma unroll
            for (int t = 0; t < 2; ++t) {
                int lt = 2 * w + t;
                float x0 = sX[lt * 65 + l], x1 = sX[lt * 65 + 32 + l];
                float s1 = x0 + x1, s2 = x0 * x0 + x1 * x1;
                #pragma unroll
                for (int o = 16; o; o >>= 1) {
                    s1 += __shfl_xor_sync(0xffffffffu, s1, o);
                    s2 += __shfl_xor_sync(0xffffffffu, s2, o);
                }
                float mu = s1 * (1.f / 64.f);
                float rs = rsqrtf(s2 * (1.f / 64.f) - mu * mu + 1e-5f);
                sHA[lt * 65 + l]      = (x0 - mu) * rs * sL2g[l]      + sL2b[l];
                sHA[lt * 65 + 32 + l] = (x1 - mu) * rs * sL2g[32 + l] + sL2b[32 + l];
            }
        }
        __syncthreads();
        {   // FC: warp -> 16 cols, lane -> token; gelu; hid -> smem pitch 257
            const int c0f = w * 16;
            unsigned long long fac[8] = {0, 0, 0, 0, 0, 0, 0, 0};
            const float* sH = sHA + l * 65;
            #pragma unroll 2
            for (int k = 0; k < 64; ++k) {
                unsigned long long h2 = bcast2(sH[k]);
                const float* wr = sWf + k * 256 + c0f;
                ulonglong2 wa = *(const ulonglong2*)(wr);
                ulonglong2 wb = *(const ulonglong2*)(wr + 4);
                ulonglong2 wc = *(const ulonglong2*)(wr + 8);
                ulonglong2 wd = *(const ulonglong2*)(wr + 12);
                fma2(fac[0], h2, wa.x); fma2(fac[1], h2, wa.y);
                fma2(fac[2], h2, wb.x); fma2(fac[3], h2, wb.y);
                fma2(fac[4], h2, wc.x); fma2(fac[5], h2, wc.y);
                fma2(fac[6], h2, wd.x); fma2(fac[7], h2, wd.y);
            }
            float f[16];
            #pragma unroll
            for (int j = 0; j < 8; ++j) upk2(fac[j], f[2 * j], f[2 * j + 1]);
            float* hr = sHid + l * 257 + c0f;
            #pragma unroll
            for (int j = 0; j < 16; ++j) {
                float z = f[j] + sBf[c0f + j];
                float u = 0.7978845608028654f * (z + 0.044715f * z * z * z);
                float e2u = __expf(2.0f * u);
                float th = 1.0f - 2.0f / (e2u + 1.0f);
                hr[j] = 0.5f * z * (1.0f + th);
            }
        }
        __syncthreads();
        {   // PR: warp -> 4 cols, lane -> token; hid from smem (conflict-free)
            const int c0p = w * 4;
            unsigned long long pac[2] = {0, 0};
            const float* hgl = sHid + l * 257;
            #pragma unroll 8
            for (int k = 0; k < 256; ++k) {
                unsigned long long h2 = bcast2(hgl[k]);
                ulonglong2 wv = *(const ulonglong2*)&sWp[k * 64 + c0p];
                fma2(pac[0], h2, wv.x); fma2(pac[1], h2, wv.y);
            }
            float p4[4];
            upk2(pac[0], p4[0], p4[1]); upk2(pac[1], p4[2], p4[3]);
            float4 bp4 = __ldg((const float4*)(bpr_ + c0p));
            float* xr = sX + l * 65 + c0p;
            xr[0] += 0.1f * (p4[0] + bp4.x);
            xr[1] += 0.1f * (p4[1] + bp4.y);
            xr[2] += 0.1f * (p4[2] + bp4.z);
            xr[3] += 0.1f * (p4[3] + bp4.w);
        }
        CLUSTER_BAR();   // bar3: hid reads done before peers push next K/V
    }

    // ================= final LN -> out =================
    {
        float g0 = __ldg(lnfg_ + l), g1 = __ldg(lnfg_ + 32 + l);
        float b0 = __ldg(lnfb_ + l), b1 = __ldg(lnfb_ + 32 + l);
        #pragma unroll
        for (int t = 0; t < 2; ++t) {
            int lt = 2 * w + t;
            float x0 = sX[lt * 65 + l], x1 = sX[lt * 65 + 32 + l];
            float s1 = x0 + x1, s2 = x0 * x0 + x1 * x1;
            #pragma unroll
            for (int o = 16; o; o >>= 1) {
                s1 += __shfl_xor_sync(0xffffffffu, s1, o);
                s2 += __shfl_xor_sync(0xffffffffu, s2, o);
            }
            float mu = s1 * (1.f / 64.f);
            float rs = rsqrtf(s2 * (1.f / 64.f) - mu * mu + 1e-5f);
            out[(t0 + lt) * 64 + l]      = (x0 - mu) * rs * g0 + b0;
            out[(t0 + lt) * 64 + 32 + l] = (x1 - mu) * rs * g1 + b1;
        }
    }
}

extern "C" void kernel_launch(void* const* d_in, const int* in_sizes, int n_in,
                              void* d_out, int out_size)
{
    (void)in_sizes; (void)n_in; (void)out_size;
    cudaFuncSetAttribute(lt37349035606833_kernel,
                         cudaFuncAttributeMaxDynamicSharedMemorySize, SMEM_BYTES);
    lt37349035606833_kernel<<<GRID, NTHREADS, SMEM_BYTES>>>(
        (const int*)  d_in[0],  (const int*)  d_in[1],
        (const float*)d_in[2],  (const float*)d_in[3],
        (const float*)d_in[4],  (const float*)d_in[5],
        (const float*)d_in[6],  (const float*)d_in[7],
        (const float*)d_in[8],  (const float*)d_in[9],
        (const float*)d_in[10], (const float*)d_in[11],
        (const float*)d_in[12], (const float*)d_in[13],
        (const float*)d_in[14], (const float*)d_in[15],
        (const float*)d_in[16], (const float*)d_in[17],
        (const float*)d_in[18], (const float*)d_in[19],
        (const float*)d_in[20], (const float*)d_in[21],
        (float*)d_out);
}

// round 12
// speedup vs baseline: 1.7361x; 1.0051x over previous
#include <cuda_runtime.h>
#include <cstdint>

#define GRID     128
#define NTHREADS 512
#define NT       4096     // B*S tokens

// ---- device globals ----
__device__ float g_TEMB[4096 * 64];
__device__ unsigned g_arrive;
__device__ volatile unsigned g_release;

// ---- smem layout (floats), 58112 = 232448 B (exact max) ----
#define OFF_WQKV 0            // [k][192]      12288
#define OFF_WFC  12288        // [k][256]      16384
#define OFF_WPR  28672        // [k(256)][64]  16384
#define OFF_B    45056        // 448: bqkv[192] bfc[256]
#define OFF_X    45504        // 32 tokens pitch 65 = 2080
#define OFF_Q    47584        // Q[128] pitch 16 = 2048 (peer-pushed, bcast reads)
#define OFF_K    49632        // K[128] pitch 17 = 2176 (peer-pushed)
#define OFF_V    51808        // V[128] pitch 17 = 2176 (peer-pushed)
#define OFF_HA   53984        // h (LN out) / A landing zone, 32x65 = 2080
#define OFF_P    56064        // softmax P, 16 warps x 128 = 2048
#define OFF_HID  49632        // Phase-C hid 32 x pitch257 = 8222 (overlays K/V/HA/P = 8480)
#define SMEM_FLOATS 58112
#define SMEM_BYTES (SMEM_FLOATS * 4)   // 232448

// ---- packed f32x2 helpers ----
__device__ __forceinline__ unsigned long long bcast2(float x) {
    unsigned long long r; asm("mov.b64 %0,{%1,%1};" : "=l"(r) : "f"(x)); return r;
}
__device__ __forceinline__ void upk2(unsigned long long v, float& x, float& y) {
    asm("mov.b64 {%0,%1},%2;" : "=f"(x), "=f"(y) : "l"(v));
}
__device__ __forceinline__ void fma2(unsigned long long& d, unsigned long long a,
                                     unsigned long long b) {
    asm("fma.rn.f32x2 %0,%1,%2,%0;" : "+l"(d) : "l"(a), "l"(b));
}

// ---- cluster helpers ----
__device__ __forceinline__ uint32_t smem_u32(const void* p) {
    uint32_t a;
    asm("{ .reg .u64 t; cvta.to.shared.u64 t, %1; cvt.u32.u64 %0, t; }" : "=r"(a) : "l"(p));
    return a;
}
__device__ __forceinline__ void sts_cluster1(uint32_t laddr, int rank, float v) {
    uint32_t r;
    asm volatile("mapa.shared::cluster.u32 %0, %1, %2;" : "=r"(r) : "r"(laddr), "r"(rank));
    asm volatile("st.shared::cluster.f32 [%0], %1;" :: "r"(r), "f"(v) : "memory");
}
#define CLUSTER_BAR() do { \
    asm volatile("barrier.cluster.arrive.aligned;" ::: "memory"); \
    asm volatile("barrier.cluster.wait.aligned;"   ::: "memory"); \
} while (0)

__device__ __forceinline__ void grid_sync(unsigned gen) {
    __syncthreads();
    if (threadIdx.x == 0) {
        __threadfence();
        unsigned prev = atomicAdd(&g_arrive, 1u);
        if (prev == gen * GRID - 1u) {
            __threadfence();
            g_release = gen;
        } else {
            while (*(volatile unsigned*)&g_release < gen) { __nanosleep(32); }
        }
        __threadfence();
    }
    __syncthreads();
}

extern "C" __global__ void __launch_bounds__(NTHREADS, 1) __cluster_dims__(4, 1, 1)
lt37349035606833_kernel(
    const int*   __restrict__ idx,   const int*   __restrict__ nloops_p,
    const float* __restrict__ wte,   const float* __restrict__ wpe,
    const float* __restrict__ tw1,   const float* __restrict__ tb1,
    const float* __restrict__ tw2,   const float* __restrict__ tb2,
    const float* __restrict__ ln1g_, const float* __restrict__ ln1b_,
    const float* __restrict__ wqkv_, const float* __restrict__ bqkv_,
    const float* __restrict__ wo_,   const float* __restrict__ bo_,
    const float* __restrict__ ln2g_, const float* __restrict__ ln2b_,
    const float* __restrict__ wfc_,  const float* __restrict__ bfc_,
    const float* __restrict__ wpr_,  const float* __restrict__ bpr_,
    const float* __restrict__ lnfg_, const float* __restrict__ lnfb_,
    float* __restrict__ out)
{
    extern __shared__ float sm[];
    const int tid = threadIdx.x;
    const int blk = blockIdx.x;
    const int w = tid >> 5, l = tid & 31;
    const int nloops = *nloops_p;
    unsigned gen = g_release;
    const uint32_t smb = smem_u32(sm);

    // ---- stage weights/biases ----
    for (int i = tid; i < 12288; i += NTHREADS) sm[OFF_WQKV + i] = wqkv_[i];
    for (int i = tid; i < 16384; i += NTHREADS) {
        sm[OFF_WFC + i] = wfc_[i];
        sm[OFF_WPR + i] = wpr_[i];
    }
    if (tid < 192)                sm[OFF_B + tid] = bqkv_[tid];
    if (tid >= 192 && tid < 448)  sm[OFF_B + tid] = bfc_[tid - 192];

    // ln gamma/beta registerized (per-lane)
    const float ln1g0 = __ldg(ln1g_ + l), ln1g1 = __ldg(ln1g_ + 32 + l);
    const float ln1b0 = __ldg(ln1b_ + l), ln1b1 = __ldg(ln1b_ + 32 + l);
    const float ln2g0 = __ldg(ln2g_ + l), ln2g1 = __ldg(ln2g_ + 32 + l);
    const float ln2b0 = __ldg(ln2b_ + l), ln2b1 = __ldg(ln2b_ + 32 + l);

    // ---- initial x tile (pitch 65) ----
    const int t0 = blk * 32;
    for (int i = tid; i < 2048; i += NTHREADS) {
        int t = i >> 6, d = i & 63;
        int tok = t0 + t;
        sm[OFF_X + t * 65 + d] = wte[idx[tok] * 64 + d] + wpe[(tok & 127) * 64 + d];
    }
    __syncthreads();

    // ---- precompute temb (scratch in K/V region; grid_sync below) ----
    {
        float* sT = sm + OFF_K;
        for (int s = blk; s < nloops; s += GRID) {
            float tt = (float)s;
            if (tid < 128) {
                float f = __expf(-9.2103403719761836f * (float)tid / 128.0f);
                float a = tt * f;
                sT[tid]       = cosf(a);
                sT[128 + tid] = sinf(a);
            }
            __syncthreads();
            for (int j = tid; j < 1024; j += NTHREADS) {
                float z = tb1[j];
                for (int k = 0; k < 256; ++k) z += sT[k] * tw1[k * 1024 + j];
                sT[256 + j] = z / (1.0f + __expf(-z));
            }
            __syncthreads();
            if (tid < 64) {
                float z = tb2[tid];
                for (int k = 0; k < 1024; ++k) z += sT[256 + k] * tw2[k * 64 + tid];
                g_TEMB[s * 64 + tid] = z;
            }
            __syncthreads();
        }
    }
    grid_sync(++gen);

    const int rc = blk & 3;                  // cluster rank == head index
    float* sX   = sm + OFF_X;
    float* sHA  = sm + OFF_HA;               // h / A landing zone
    float* sHid = sm + OFF_HID;              // Phase-C hid (overlays K/V/HA/P)
    const float* sQ = sm + OFF_Q;
    const float* sK = sm + OFF_K;
    const float* sV = sm + OFF_V;
    const float* sWq = sm + OFF_WQKV;
    const float* sWf = sm + OFF_WFC;
    const float* sWp = sm + OFF_WPR;
    const float* sBq = sm + OFF_B;
    const float* sBf = sm + OFF_B + 192;

    // temb prefetch for it = 0
    float tv0 = __ldg(g_TEMB + l), tv1 = __ldg(g_TEMB + 32 + l);

    for (int it = 0; it < nloops; ++it) {
        // ============ Phase A: x += temb; LN1 -> sHA; QKV + push ============
        {
            #pragma unroll
            for (int t = 0; t < 2; ++t) {
                int lt = w * 2 + t;
                float x0 = sX[lt * 65 + l]      + tv0;
                float x1 = sX[lt * 65 + 32 + l] + tv1;
                sX[lt * 65 + l]      = x0;
                sX[lt * 65 + 32 + l] = x1;
                float s1 = x0 + x1, s2 = x0 * x0 + x1 * x1;
                #pragma unroll
                for (int o = 16; o; o >>= 1) {
                    s1 += __shfl_xor_sync(0xffffffffu, s1, o);
                    s2 += __shfl_xor_sync(0xffffffffu, s2, o);
                }
                float mu = s1 * (1.0f / 64.0f);
                float rs = rsqrtf(s2 * (1.0f / 64.0f) - mu * mu + 1e-5f);
                sHA[lt * 65 + l]      = (x0 - mu) * rs * ln1g0 + ln1b0;
                sHA[lt * 65 + 32 + l] = (x1 - mu) * rs * ln1g1 + ln1b1;
            }
        }
        __syncthreads();
        {   // QKV GEMM: warp -> 12 cols, lane -> token; push Q/K/V via DSMEM
            const int c0 = w * 12;
            const float* hAl = sHA + l * 65;
            unsigned long long acc[6] = {0, 0, 0, 0, 0, 0};
            #pragma unroll 4
            for (int k = 0; k < 64; ++k) {
                unsigned long long h2 = bcast2(hAl[k]);
                const float* wr = sWq + k * 192 + c0;
                ulonglong2 wa = *(const ulonglong2*)(wr);
                ulonglong2 wb = *(const ulonglong2*)(wr + 4);
                ulonglong2 wc = *(const ulonglong2*)(wr + 8);
                fma2(acc[0], h2, wa.x); fma2(acc[1], h2, wa.y);
                fma2(acc[2], h2, wb.x); fma2(acc[3], h2, wb.y);
                fma2(acc[4], h2, wc.x); fma2(acc[5], h2, wc.y);
            }
            float c[12];
            #pragma unroll
            for (int j = 0; j < 6; ++j) upk2(acc[j], c[2 * j], c[2 * j + 1]);
            const int tkb = rc * 32 + l;     // token within batch (0..127)
            #pragma unroll
            for (int g3 = 0; g3 < 3; ++g3) {
                int cg = c0 + 4 * g3;
                float v0 = c[4*g3]   + sBq[cg];
                float v1 = c[4*g3+1] + sBq[cg+1];
                float v2 = c[4*g3+2] + sBq[cg+2];
                float v3 = c[4*g3+3] + sBq[cg+3];
                uint32_t a; int tr;
                if (cg < 64) {
                    tr = cg >> 4;
                    a = smb + (OFF_Q + tkb * 16 + (cg & 15)) * 4;
                } else if (cg < 128) {
                    tr = (cg - 64) >> 4;
                    a = smb + (OFF_K + tkb * 17 + ((cg - 64) & 15)) * 4;
                } else {
                    tr = (cg - 128) >> 4;
                    a = smb + (OFF_V + tkb * 17 + ((cg - 128) & 15)) * 4;
                }
                sts_cluster1(a,      tr, v0);
                sts_cluster1(a + 4,  tr, v1);
                sts_cluster1(a + 8,  tr, v2);
                sts_cluster1(a + 12, tr, v3);
            }
        }
        CLUSTER_BAR();   // bar1: Q/K/V delivered everywhere

        // ============ Phase B: attention for head rc; Q/K/V local ============
        {
            float* sP = sm + OFF_P + w * 128;
            const int d = l & 15, half = l >> 4;
            #pragma unroll 1
            for (int r = 0; r < 8; ++r) {
                const int qt = w + 16 * r;          // interleaved -> warp balance
                const int gq = qt >> 5;
                const float* qb = sQ + qt * 16;     // broadcast LDS.128 x4
                float4 qa = *(const float4*)(qb);
                float4 qbv = *(const float4*)(qb + 4);
                float4 qc = *(const float4*)(qb + 8);
                float4 qd = *(const float4*)(qb + 12);
                float q[16] = {qa.x, qa.y, qa.z, qa.w, qbv.x, qbv.y, qbv.z, qbv.w,
                               qc.x, qc.y, qc.z, qc.w, qd.x, qd.y, qd.z, qd.w};
                float e[4];
                float mx = -1e30f;
                #pragma unroll
                for (int g = 0; g < 4; ++g) {
                    if (g > gq) break;
                    const float* Kr = sK + (32 * g + l) * 17;
                    float s = 0.f;
                    #pragma unroll
                    for (int dd = 0; dd < 16; ++dd) s += q[dd] * Kr[dd];
                    s = s * 0.25f + ((32 * g + l <= qt) ? 0.f : -1e9f);
                    e[g] = s;
                    mx = fmaxf(mx, s);
                }
                #pragma unroll
                for (int o = 16; o; o >>= 1) mx = fmaxf(mx, __shfl_xor_sync(0xffffffffu, mx, o));
                float es = 0.f;
                #pragma unroll
                for (int g = 0; g < 4; ++g) {
                    if (g > gq) break;
                    e[g] = __expf(e[g] - mx);
                    es += e[g];
                }
                #pragma unroll
                for (int o = 16; o; o >>= 1) es += __shfl_xor_sync(0xffffffffu, es, o);
                float inv = 1.0f / es;
                #pragma unroll
                for (int g = 0; g < 4; ++g) {
                    if (g > gq) break;
                    sP[32 * g + l] = e[g] * inv;
                }
                __syncwarp();
                float ov = 0.f;
                #pragma unroll
                for (int i = 0; i < 2; ++i) {
                    int g = half + 2 * i;
                    if (g <= gq) {
                        const float* Pg = sP + 32 * g;
                        const float* Vg = sV + (32 * g) * 17 + d;
                        const float* P1 = Pg + 16 * half;
                        const float* V1 = Vg + (16 * half) * 17;
                        const float* P2 = Pg + 16 - 16 * half;
                        const float* V2 = Vg + (16 - 16 * half) * 17;
                        float pv = 0.f;
                        #pragma unroll
                        for (int k2 = 0; k2 < 16; ++k2) pv += P1[k2] * V1[k2 * 17];
                        #pragma unroll
                        for (int k2 = 0; k2 < 16; ++k2) pv += P2[k2] * V2[k2 * 17];
                        ov += pv;
                    }
                }
                ov += __shfl_xor_sync(0xffffffffu, ov, 16);
                if (half == 0) {   // push A to token-owner CTA's sHA
                    sts_cluster1(smb + (OFF_HA + (qt & 31) * 65 + rc * 16 + d) * 4,
                                 qt >> 5, ov);
                }
                __syncwarp();
            }
        }
        CLUSTER_BAR();   // bar2: A delivered everywhere; Q/K/V/P dead from here

        // ============ Phase C: o-proj + LN2 + MLP (lane = token) ============
        {   // o-proj: warp -> 4 cols, lane -> token; A already in sHA
            const int c0o = w * 4;
            unsigned long long oac[2] = {0, 0};
            const float* sA = sHA + l * 65;
            #pragma unroll 4
            for (int k = 0; k < 64; ++k) {
                unsigned long long a2 = bcast2(sA[k]);
                ulonglong2 wv = __ldg((const ulonglong2*)&wo_[k * 64 + c0o]);
                fma2(oac[0], a2, wv.x); fma2(oac[1], a2, wv.y);
            }
            float o4[4];
            upk2(oac[0], o4[0], o4[1]); upk2(oac[1], o4[2], o4[3]);
            float4 bo4 = __ldg((const float4*)(bo_ + c0o));
            float* xr = sX + l * 65 + c0o;
            xr[0] += 0.1f * (o4[0] + bo4.x);
            xr[1] += 0.1f * (o4[1] + bo4.y);
            xr[2] += 0.1f * (o4[2] + bo4.z);
            xr[3] += 0.1f * (o4[3] + bo4.w);
        }
        __syncthreads();
        {   // LN2: 2 tokens/warp -> h in sHA (A fully consumed)
            #pragma unroll
            for (int t = 0; t < 2; ++t) {
                int lt = 2 * w + t;
                float x0 = sX[lt * 65 + l], x1 = sX[lt * 65 + 32 + l];
                float s1 = x0 + x1, s2 = x0 * x0 + x1 * x1;
                #pragma unroll
                for (int o = 16; o; o >>= 1) {
                    s1 += __shfl_xor_sync(0xffffffffu, s1, o);
                    s2 += __shfl_xor_sync(0xffffffffu, s2, o);
                }
                float mu = s1 * (1.f / 64.f);
                float rs = rsqrtf(s2 * (1.f / 64.f) - mu * mu + 1e-5f);
                sHA[lt * 65 + l]      = (x0 - mu) * rs * ln2g0 + ln2b0;
                sHA[lt * 65 + 32 + l] = (x1 - mu) * rs * ln2g1 + ln2b1;
            }
        }
        __syncthreads();
        float gl[16];
        {   // FC: warp -> 16 cols, lane -> token; gelu in regs
            const int c0f = w * 16;
            unsigned long long fac[8] = {0, 0, 0, 0, 0, 0, 0, 0};
            const float* sH = sHA + l * 65;
            #pragma unroll 2
            for (int k = 0; k < 64; ++k) {
                unsigned long long h2 = bcast2(sH[k]);
                const float* wr = sWf + k * 256 + c0f;
                ulonglong2 wa = *(const ulonglong2*)(wr);
                ulonglong2 wb = *(const ulonglong2*)(wr + 4);
                ulonglong2 wc = *(const ulonglong2*)(wr + 8);
                ulonglong2 wd = *(const ulonglong2*)(wr + 12);
                fma2(fac[0], h2, wa.x); fma2(fac[1], h2, wa.y);
                fma2(fac[2], h2, wb.x); fma2(fac[3], h2, wb.y);
                fma2(fac[4], h2, wc.x); fma2(fac[5], h2, wc.y);
                fma2(fac[6], h2, wd.x); fma2(fac[7], h2, wd.y);
            }
            float f[16];
            #pragma unroll
            for (int j = 0; j < 8; ++j) upk2(fac[j], f[2 * j], f[2 * j + 1]);
            #pragma unroll
            for (int j = 0; j < 16; ++j) {
                float z = f[j] + sBf[c0f + j];
                float u = 0.7978845608028654f * (z + 0.044715f * z * z * z);
                float e2u = __expf(2.0f * u);
                float th = 1.0f - 2.0f / (e2u + 1.0f);
                gl[j] = 0.5f * z * (1.0f + th);
            }
        }
        __syncthreads();   // all h reads done before hid overwrites HA region
        {   // store hid at pitch 257 (overlays K/V/HA/P)
            const int c0f = w * 16;
            float* hr = sHid + l * 257 + c0f;
            #pragma unroll
            for (int j = 0; j < 16; ++j) hr[j] = gl[j];
        }
        __syncthreads();
        {   // PR: warp -> 4 cols, lane -> token; hid from smem (conflict-free)
            const int c0p = w * 4;
            unsigned long long pac[2] = {0, 0};
            const float* hgl = sHid + l * 257;
            #pragma unroll 8
            for (int k = 0; k < 256; ++k) {
                unsigned long long h2 = bcast2(hgl[k]);
                ulonglong2 wv = *(const ulonglong2*)&sWp[k * 64 + c0p];
                fma2(pac[0], h2, wv.x); fma2(pac[1], h2, wv.y);
            }
            float p4[4];
            upk2(pac[0], p4[0], p4[1]); upk2(pac[1], p4[2], p4[3]);
            float4 bp4 = __ldg((const float4*)(bpr_ + c0p));
            float* xr = sX + l * 65 + c0p;
            xr[0] += 0.1f * (p4[0] + bp4.x);
            xr[1] += 0.1f * (p4[1] + bp4.y);
            xr[2] += 0.1f * (p4[2] + bp4.z);
            xr[3] += 0.1f * (p4[3] + bp4.w);
        }
        {   // prefetch temb for next iter (hides L2 latency behind bar3)
            int itn = (it + 1 < nloops) ? it + 1 : it;
            tv0 = __ldg(g_TEMB + itn * 64 + l);
            tv1 = __ldg(g_TEMB + itn * 64 + 32 + l);
        }
        CLUSTER_BAR();   // bar3: hid reads done before peers push next Q/K/V
    }

    // ================= final LN -> out =================
    {
        float g0 = __ldg(lnfg_ + l), g1 = __ldg(lnfg_ + 32 + l);
        float b0 = __ldg(lnfb_ + l), b1 = __ldg(lnfb_ + 32 + l);
        #pragma unroll
        for (int t = 0; t < 2; ++t) {
            int lt = 2 * w + t;
            float x0 = sX[lt * 65 + l], x1 = sX[lt * 65 + 32 + l];
            float s1 = x0 + x1, s2 = x0 * x0 + x1 * x1;
            #pragma unroll
            for (int o = 16; o; o >>= 1) {
                s1 += __shfl_xor_sync(0xffffffffu, s1, o);
                s2 += __shfl_xor_sync(0xffffffffu, s2, o);
            }
            float mu = s1 * (1.f / 64.f);
            float rs = rsqrtf(s2 * (1.f / 64.f) - mu * mu + 1e-5f);
            out[(t0 + lt) * 64 + l]      = (x0 - mu) * rs * g0 + b0;
            out[(t0 + lt) * 64 + 32 + l] = (x1 - mu) * rs * g1 + b1;
        }
    }
}

extern "C" void kernel_launch(void* const* d_in, const int* in_sizes, int n_in,
                              void* d_out, int out_size)
{
    (void)in_sizes; (void)n_in; (void)out_size;
    cudaFuncSetAttribute(lt37349035606833_kernel,
                         cudaFuncAttributeMaxDynamicSharedMemorySize, SMEM_BYTES);
    lt37349035606833_kernel<<<GRID, NTHREADS, SMEM_BYTES>>>(
        (const int*)  d_in[0],  (const int*)  d_in[1],
        (const float*)d_in[2],  (const float*)d_in[3],
        (const float*)d_in[4],  (const float*)d_in[5],
        (const float*)d_in[6],  (const float*)d_in[7],
        (const float*)d_in[8],  (const float*)d_in[9],
        (const float*)d_in[10], (const float*)d_in[11],
        (const float*)d_in[12], (const float*)d_in[13],
        (const float*)d_in[14], (const float*)d_in[15],
        (const float*)d_in[16], (const float*)d_in[17],
        (const float*)d_in[18], (const float*)d_in[19],
        (const float*)d_in[20], (const float*)d_in[21],
        (float*)d_out);
}

// round 13
// speedup vs baseline: 1.7393x; 1.0018x over previous
#include <cuda_runtime.h>
#include <cstdint>

#define GRID     128
#define NTHREADS 512
#define NT       4096     // B*S tokens

// ---- device globals ----
__device__ float g_TEMB[4096 * 64];
__device__ unsigned g_arrive;
__device__ volatile unsigned g_release;

// ---- smem layout (floats), 58112 = 232448 B (exact max) ----
#define OFF_WQKV 0            // [k][192]      12288
#define OFF_WFC  12288        // [k][256]      16384
#define OFF_WPR  28672        // [k(256)][64]  16384
#define OFF_B    45056        // 448: bqkv[192] bfc[256]
#define OFF_X    45504        // 32 tokens pitch 65 = 2080
#define OFF_Q    47584        // Q[128] pitch 16 = 2048 (peer-pushed, bcast reads)
#define OFF_K    49632        // K[128] pitch 17 = 2176 (peer-pushed)
#define OFF_V    51808        // V[128] pitch 17 = 2176 (peer-pushed)
#define OFF_HA   53984        // h (LN out) / A landing zone, 32x65 = 2080
#define OFF_P    56064        // softmax P, 16 warps x 128 = 2048
#define OFF_HID  49632        // Phase-C hid 32 x pitch257 = 8222 (overlays K/V/HA/P = 8480)
#define SMEM_FLOATS 58112
#define SMEM_BYTES (SMEM_FLOATS * 4)   // 232448

// ---- packed f32x2 helpers ----
__device__ __forceinline__ unsigned long long bcast2(float x) {
    unsigned long long r; asm("mov.b64 %0,{%1,%1};" : "=l"(r) : "f"(x)); return r;
}
__device__ __forceinline__ void upk2(unsigned long long v, float& x, float& y) {
    asm("mov.b64 {%0,%1},%2;" : "=f"(x), "=f"(y) : "l"(v));
}
__device__ __forceinline__ void fma2(unsigned long long& d, unsigned long long a,
                                     unsigned long long b) {
    asm("fma.rn.f32x2 %0,%1,%2,%0;" : "+l"(d) : "l"(a), "l"(b));
}

// ---- cluster helpers ----
__device__ __forceinline__ uint32_t smem_u32(const void* p) {
    uint32_t a;
    asm("{ .reg .u64 t; cvta.to.shared.u64 t, %1; cvt.u32.u64 %0, t; }" : "=r"(a) : "l"(p));
    return a;
}
__device__ __forceinline__ void sts_cluster1(uint32_t laddr, int rank, float v) {
    uint32_t r;
    asm volatile("mapa.shared::cluster.u32 %0, %1, %2;" : "=r"(r) : "r"(laddr), "r"(rank));
    asm volatile("st.shared::cluster.f32 [%0], %1;" :: "r"(r), "f"(v) : "memory");
}
#define CLUSTER_BAR() do { \
    asm volatile("barrier.cluster.arrive.aligned;" ::: "memory"); \
    asm volatile("barrier.cluster.wait.aligned;"   ::: "memory"); \
} while (0)

__device__ __forceinline__ void grid_sync(unsigned gen) {
    __syncthreads();
    if (threadIdx.x == 0) {
        __threadfence();
        unsigned prev = atomicAdd(&g_arrive, 1u);
        if (prev == gen * GRID - 1u) {
            __threadfence();
            g_release = gen;
        } else {
            while (*(volatile unsigned*)&g_release < gen) { __nanosleep(32); }
        }
        __threadfence();
    }
    __syncthreads();
}

extern "C" __global__ void __launch_bounds__(NTHREADS, 1) __cluster_dims__(4, 1, 1)
lt37349035606833_kernel(
    const int*   __restrict__ idx,   const int*   __restrict__ nloops_p,
    const float* __restrict__ wte,   const float* __restrict__ wpe,
    const float* __restrict__ tw1,   const float* __restrict__ tb1,
    const float* __restrict__ tw2,   const float* __restrict__ tb2,
    const float* __restrict__ ln1g_, const float* __restrict__ ln1b_,
    const float* __restrict__ wqkv_, const float* __restrict__ bqkv_,
    const float* __restrict__ wo_,   const float* __restrict__ bo_,
    const float* __restrict__ ln2g_, const float* __restrict__ ln2b_,
    const float* __restrict__ wfc_,  const float* __restrict__ bfc_,
    const float* __restrict__ wpr_,  const float* __restrict__ bpr_,
    const float* __restrict__ lnfg_, const float* __restrict__ lnfb_,
    float* __restrict__ out)
{
    extern __shared__ float sm[];
    const int tid = threadIdx.x;
    const int blk = blockIdx.x;
    const int w = tid >> 5, l = tid & 31;
    const int nloops = *nloops_p;
    unsigned gen = g_release;
    const uint32_t smb = smem_u32(sm);

    // ---- stage weights/biases ----
    for (int i = tid; i < 12288; i += NTHREADS) sm[OFF_WQKV + i] = wqkv_[i];
    for (int i = tid; i < 16384; i += NTHREADS) {
        sm[OFF_WFC + i] = wfc_[i];
        sm[OFF_WPR + i] = wpr_[i];
    }
    if (tid < 192)                sm[OFF_B + tid] = bqkv_[tid];
    if (tid >= 192 && tid < 448)  sm[OFF_B + tid] = bfc_[tid - 192];

    // ln gamma/beta registerized (per-lane)
    const float ln1g0 = __ldg(ln1g_ + l), ln1g1 = __ldg(ln1g_ + 32 + l);
    const float ln1b0 = __ldg(ln1b_ + l), ln1b1 = __ldg(ln1b_ + 32 + l);
    const float ln2g0 = __ldg(ln2g_ + l), ln2g1 = __ldg(ln2g_ + 32 + l);
    const float ln2b0 = __ldg(ln2b_ + l), ln2b1 = __ldg(ln2b_ + 32 + l);

    // ---- initial x tile (pitch 65) ----
    const int t0 = blk * 32;
    for (int i = tid; i < 2048; i += NTHREADS) {
        int t = i >> 6, d = i & 63;
        int tok = t0 + t;
        sm[OFF_X + t * 65 + d] = wte[idx[tok] * 64 + d] + wpe[(tok & 127) * 64 + d];
    }
    __syncthreads();

    // ---- precompute temb (scratch in K/V region; grid_sync below) ----
    {
        float* sT = sm + OFF_K;
        for (int s = blk; s < nloops; s += GRID) {
            float tt = (float)s;
            if (tid < 128) {
                float f = __expf(-9.2103403719761836f * (float)tid / 128.0f);
                float a = tt * f;
                sT[tid]       = cosf(a);
                sT[128 + tid] = sinf(a);
            }
            __syncthreads();
            for (int j = tid; j < 1024; j += NTHREADS) {
                float z = tb1[j];
                for (int k = 0; k < 256; ++k) z += sT[k] * tw1[k * 1024 + j];
                sT[256 + j] = z / (1.0f + __expf(-z));
            }
            __syncthreads();
            if (tid < 64) {
                float z = tb2[tid];
                for (int k = 0; k < 1024; ++k) z += sT[256 + k] * tw2[k * 64 + tid];
                g_TEMB[s * 64 + tid] = z;
            }
            __syncthreads();
        }
    }
    grid_sync(++gen);

    const int rc = blk & 3;                  // cluster rank == head index
    float* sX   = sm + OFF_X;
    float* sHA  = sm + OFF_HA;               // h / A landing zone
    float* sHid = sm + OFF_HID;              // Phase-C hid (overlays K/V/HA/P)
    const float* sQ = sm + OFF_Q;
    const float* sK = sm + OFF_K;
    const float* sV = sm + OFF_V;
    const float* sWq = sm + OFF_WQKV;
    const float* sWf = sm + OFF_WFC;
    const float* sWp = sm + OFF_WPR;
    const float* sBq = sm + OFF_B;
    const float* sBf = sm + OFF_B + 192;

    // temb prefetch for it = 0
    float tv0 = __ldg(g_TEMB + l), tv1 = __ldg(g_TEMB + 32 + l);

    for (int it = 0; it < nloops; ++it) {
        // ============ Phase A: x += temb; LN1 -> sHA; QKV + push ============
        {
            #pragma unroll
            for (int t = 0; t < 2; ++t) {
                int lt = w * 2 + t;
                float x0 = sX[lt * 65 + l]      + tv0;
                float x1 = sX[lt * 65 + 32 + l] + tv1;
                sX[lt * 65 + l]      = x0;
                sX[lt * 65 + 32 + l] = x1;
                float s1 = x0 + x1, s2 = x0 * x0 + x1 * x1;
                #pragma unroll
                for (int o = 16; o; o >>= 1) {
                    s1 += __shfl_xor_sync(0xffffffffu, s1, o);
                    s2 += __shfl_xor_sync(0xffffffffu, s2, o);
                }
                float mu = s1 * (1.0f / 64.0f);
                float rs = rsqrtf(s2 * (1.0f / 64.0f) - mu * mu + 1e-5f);
                sHA[lt * 65 + l]      = (x0 - mu) * rs * ln1g0 + ln1b0;
                sHA[lt * 65 + 32 + l] = (x1 - mu) * rs * ln1g1 + ln1b1;
            }
        }
        __syncthreads();
        {   // QKV GEMM: warp -> 12 cols, lane -> token; push Q/K/V via DSMEM
            const int c0 = w * 12;
            const float* hAl = sHA + l * 65;
            unsigned long long acc[6] = {0, 0, 0, 0, 0, 0};
            #pragma unroll 4
            for (int k = 0; k < 64; ++k) {
                unsigned long long h2 = bcast2(hAl[k]);
                const float* wr = sWq + k * 192 + c0;
                ulonglong2 wa = *(const ulonglong2*)(wr);
                ulonglong2 wb = *(const ulonglong2*)(wr + 4);
                ulonglong2 wc = *(const ulonglong2*)(wr + 8);
                fma2(acc[0], h2, wa.x); fma2(acc[1], h2, wa.y);
                fma2(acc[2], h2, wb.x); fma2(acc[3], h2, wb.y);
                fma2(acc[4], h2, wc.x); fma2(acc[5], h2, wc.y);
            }
            float c[12];
            #pragma unroll
            for (int j = 0; j < 6; ++j) upk2(acc[j], c[2 * j], c[2 * j + 1]);
            const int tkb = rc * 32 + l;     // token within batch (0..127)
            #pragma unroll
            for (int g3 = 0; g3 < 3; ++g3) {
                int cg = c0 + 4 * g3;
                float v0 = c[4*g3]   + sBq[cg];
                float v1 = c[4*g3+1] + sBq[cg+1];
                float v2 = c[4*g3+2] + sBq[cg+2];
                float v3 = c[4*g3+3] + sBq[cg+3];
                uint32_t a; int tr;
                if (cg < 64) {
                    tr = cg >> 4;
                    a = smb + (OFF_Q + tkb * 16 + (cg & 15)) * 4;
                } else if (cg < 128) {
                    tr = (cg - 64) >> 4;
                    a = smb + (OFF_K + tkb * 17 + ((cg - 64) & 15)) * 4;
                } else {
                    tr = (cg - 128) >> 4;
                    a = smb + (OFF_V + tkb * 17 + ((cg - 128) & 15)) * 4;
                }
                sts_cluster1(a,      tr, v0);
                sts_cluster1(a + 4,  tr, v1);
                sts_cluster1(a + 8,  tr, v2);
                sts_cluster1(a + 12, tr, v3);
            }
        }
        CLUSTER_BAR();   // bar1: Q/K/V delivered everywhere

        // ============ Phase B: attention for head rc; Q/K/V local ============
        {
            float* sP = sm + OFF_P + w * 128;
            const int d = l & 15, half = l >> 4;
            #pragma unroll 1
            for (int r = 0; r < 8; ++r) {
                const int qt = w + 16 * r;          // interleaved -> warp balance
                const int gq = qt >> 5;
                const float* qb = sQ + qt * 16;     // broadcast LDS.128 x4
                float4 qa = *(const float4*)(qb);
                float4 qbv = *(const float4*)(qb + 4);
                float4 qc = *(const float4*)(qb + 8);
                float4 qd = *(const float4*)(qb + 12);
                float q[16] = {qa.x, qa.y, qa.z, qa.w, qbv.x, qbv.y, qbv.z, qbv.w,
                               qc.x, qc.y, qc.z, qc.w, qd.x, qd.y, qd.z, qd.w};
                float e[4];
                float mx = -1e30f;
                #pragma unroll
                for (int g = 0; g < 4; ++g) {
                    if (g > gq) break;
                    const float* Kr = sK + (32 * g + l) * 17;
                    float s = 0.f;
                    #pragma unroll
                    for (int dd = 0; dd < 16; ++dd) s += q[dd] * Kr[dd];
                    s = s * 0.25f + ((32 * g + l <= qt) ? 0.f : -1e9f);
                    e[g] = s;
                    mx = fmaxf(mx, s);
                }
                #pragma unroll
                for (int o = 16; o; o >>= 1) mx = fmaxf(mx, __shfl_xor_sync(0xffffffffu, mx, o));
                float es = 0.f;
                #pragma unroll
                for (int g = 0; g < 4; ++g) {
                    if (g > gq) break;
                    e[g] = __expf(e[g] - mx);
                    es += e[g];
                }
                #pragma unroll
                for (int o = 16; o; o >>= 1) es += __shfl_xor_sync(0xffffffffu, es, o);
                float inv = 1.0f / es;
                #pragma unroll
                for (int g = 0; g < 4; ++g) {
                    if (g > gq) break;
                    sP[32 * g + l] = e[g] * inv;
                }
                __syncwarp();
                float ov = 0.f;
                #pragma unroll
                for (int i = 0; i < 2; ++i) {
                    int g = half + 2 * i;
                    if (g <= gq) {
                        const float* Pg = sP + 32 * g;
                        const float* Vg = sV + (32 * g) * 17 + d;
                        const float* P1 = Pg + 16 * half;
                        const float* V1 = Vg + (16 * half) * 17;
                        const float* P2 = Pg + 16 - 16 * half;
                        const float* V2 = Vg + (16 - 16 * half) * 17;
                        float pv = 0.f;
                        #pragma unroll
                        for (int k2 = 0; k2 < 16; ++k2) pv += P1[k2] * V1[k2 * 17];
                        #pragma unroll
                        for (int k2 = 0; k2 < 16; ++k2) pv += P2[k2] * V2[k2 * 17];
                        ov += pv;
                    }
                }
                ov += __shfl_xor_sync(0xffffffffu, ov, 16);
                if (half == 0) {   // push A to token-owner CTA's sHA
                    sts_cluster1(smb + (OFF_HA + (qt & 31) * 65 + rc * 16 + d) * 4,
                                 qt >> 5, ov);
                }
                __syncwarp();
            }
        }
        CLUSTER_BAR();   // bar2: A delivered everywhere; Q/K/V/P dead from here

        // ============ Phase C: o-proj + LN2 + MLP (lane = token) ============
        {   // o-proj: warp -> 4 cols, lane -> token; A already in sHA
            const int c0o = w * 4;
            unsigned long long oac[2] = {0, 0};
            const float* sA = sHA + l * 65;
            #pragma unroll 4
            for (int k = 0; k < 64; ++k) {
                unsigned long long a2 = bcast2(sA[k]);
                ulonglong2 wv = __ldg((const ulonglong2*)&wo_[k * 64 + c0o]);
                fma2(oac[0], a2, wv.x); fma2(oac[1], a2, wv.y);
            }
            float o4[4];
            upk2(oac[0], o4[0], o4[1]); upk2(oac[1], o4[2], o4[3]);
            float4 bo4 = __ldg((const float4*)(bo_ + c0o));
            float* xr = sX + l * 65 + c0o;
            xr[0] += 0.1f * (o4[0] + bo4.x);
            xr[1] += 0.1f * (o4[1] + bo4.y);
            xr[2] += 0.1f * (o4[2] + bo4.z);
            xr[3] += 0.1f * (o4[3] + bo4.w);
        }
        __syncthreads();
        {   // LN2: 2 tokens/warp -> h in sHA (A fully consumed)
            #pragma unroll
            for (int t = 0; t < 2; ++t) {
                int lt = 2 * w + t;
                float x0 = sX[lt * 65 + l], x1 = sX[lt * 65 + 32 + l];
                float s1 = x0 + x1, s2 = x0 * x0 + x1 * x1;
                #pragma unroll
                for (int o = 16; o; o >>= 1) {
                    s1 += __shfl_xor_sync(0xffffffffu, s1, o);
                    s2 += __shfl_xor_sync(0xffffffffu, s2, o);
                }
                float mu = s1 * (1.f / 64.f);
                float rs = rsqrtf(s2 * (1.f / 64.f) - mu * mu + 1e-5f);
                sHA[lt * 65 + l]      = (x0 - mu) * rs * ln2g0 + ln2b0;
                sHA[lt * 65 + 32 + l] = (x1 - mu) * rs * ln2g1 + ln2b1;
            }
        }
        __syncthreads();
        float gl[16];
        {   // FC: warp -> 16 cols, lane -> token; gelu in regs
            const int c0f = w * 16;
            unsigned long long fac[8] = {0, 0, 0, 0, 0, 0, 0, 0};
            const float* sH = sHA + l * 65;
            #pragma unroll 2
            for (int k = 0; k < 64; ++k) {
                unsigned long long h2 = bcast2(sH[k]);
                const float* wr = sWf + k * 256 + c0f;
                ulonglong2 wa = *(const ulonglong2*)(wr);
                ulonglong2 wb = *(const ulonglong2*)(wr + 4);
                ulonglong2 wc = *(const ulonglong2*)(wr + 8);
                ulonglong2 wd = *(const ulonglong2*)(wr + 12);
                fma2(fac[0], h2, wa.x); fma2(fac[1], h2, wa.y);
                fma2(fac[2], h2, wb.x); fma2(fac[3], h2, wb.y);
                fma2(fac[4], h2, wc.x); fma2(fac[5], h2, wc.y);
                fma2(fac[6], h2, wd.x); fma2(fac[7], h2, wd.y);
            }
            float f[16];
            #pragma unroll
            for (int j = 0; j < 8; ++j) upk2(fac[j], f[2 * j], f[2 * j + 1]);
            #pragma unroll
            for (int j = 0; j < 16; ++j) {
                float z = f[j] + sBf[c0f + j];
                float u = 0.7978845608028654f * (z + 0.044715f * z * z * z);
                float e2u = __expf(2.0f * u);
                float th = 1.0f - 2.0f / (e2u + 1.0f);
                gl[j] = 0.5f * z * (1.0f + th);
            }
        }
        __syncthreads();   // all h reads done before hid overwrites HA region
        {   // store hid at pitch 257 (overlays K/V/HA/P)
            const int c0f = w * 16;
            float* hr = sHid + l * 257 + c0f;
            #pragma unroll
            for (int j = 0; j < 16; ++j) hr[j] = gl[j];
        }
        __syncthreads();
        {   // PR: warp -> 4 cols, lane -> token; hid from smem (conflict-free)
            const int c0p = w * 4;
            unsigned long long pac[2] = {0, 0};
            const float* hgl = sHid + l * 257;
            #pragma unroll 8
            for (int k = 0; k < 256; ++k) {
                unsigned long long h2 = bcast2(hgl[k]);
                ulonglong2 wv = *(const ulonglong2*)&sWp[k * 64 + c0p];
                fma2(pac[0], h2, wv.x); fma2(pac[1], h2, wv.y);
            }
            float p4[4];
            upk2(pac[0], p4[0], p4[1]); upk2(pac[1], p4[2], p4[3]);
            float4 bp4 = __ldg((const float4*)(bpr_ + c0p));
            float* xr = sX + l * 65 + c0p;
            xr[0] += 0.1f * (p4[0] + bp4.x);
            xr[1] += 0.1f * (p4[1] + bp4.y);
            xr[2] += 0.1f * (p4[2] + bp4.z);
            xr[3] += 0.1f * (p4[3] + bp4.w);
        }
        {   // prefetch temb for next iter (hides L2 latency behind bar3)
            int itn = (it + 1 < nloops) ? it + 1 : it;
            tv0 = __ldg(g_TEMB + itn * 64 + l);
            tv1 = __ldg(g_TEMB + itn * 64 + 32 + l);
        }
        CLUSTER_BAR();   // bar3: hid reads done before peers push next Q/K/V
    }

    // ================= final LN -> out =================
    {
        float g0 = __ldg(lnfg_ + l), g1 = __ldg(lnfg_ + 32 + l);
        float b0 = __ldg(lnfb_ + l), b1 = __ldg(lnfb_ + 32 + l);
        #pragma unroll
        for (int t = 0; t < 2; ++t) {
            int lt = 2 * w + t;
            float x0 = sX[lt * 65 + l], x1 = sX[lt * 65 + 32 + l];
            float s1 = x0 + x1, s2 = x0 * x0 + x1 * x1;
            #pragma unroll
            for (int o = 16; o; o >>= 1) {
                s1 += __shfl_xor_sync(0xffffffffu, s1, o);
                s2 += __shfl_xor_sync(0xffffffffu, s2, o);
            }
            float mu = s1 * (1.f / 64.f);
            float rs = rsqrtf(s2 * (1.f / 64.f) - mu * mu + 1e-5f);
            out[(t0 + lt) * 64 + l]      = (x0 - mu) * rs * g0 + b0;
            out[(t0 + lt) * 64 + 32 + l] = (x1 - mu) * rs * g1 + b1;
        }
    }
}

extern "C" void kernel_launch(void* const* d_in, const int* in_sizes, int n_in,
                              void* d_out, int out_size)
{
    (void)in_sizes; (void)n_in; (void)out_size;
    cudaFuncSetAttribute(lt37349035606833_kernel,
                         cudaFuncAttributeMaxDynamicSharedMemorySize, SMEM_BYTES);
    lt37349035606833_kernel<<<GRID, NTHREADS, SMEM_BYTES>>>(
        (const int*)  d_in[0],  (const int*)  d_in[1],
        (const float*)d_in[2],  (const float*)d_in[3],
        (const float*)d_in[4],  (const float*)d_in[5],
        (const float*)d_in[6],  (const float*)d_in[7],
        (const float*)d_in[8],  (const float*)d_in[9],
        (const float*)d_in[10], (const float*)d_in[11],
        (const float*)d_in[12], (const float*)d_in[13],
        (const float*)d_in[14], (const float*)d_in[15],
        (const float*)d_in[16], (const float*)d_in[17],
        (const float*)d_in[18], (const float*)d_in[19],
        (const float*)d_in[20], (const float*)d_in[21],
        (float*)d_out);
}